// round 3
// baseline (speedup 1.0000x reference)
#include <cuda_runtime.h>
#include <math.h>

#define B_  8
#define S_  1024
#define D_  1024
#define H_  16
#define DK_ 64
#define M_  (B_ * S_)   // 8192

// ---------------- scratch (static device allocations; no cudaMalloc) --------
__device__ float g_q[B_ * H_ * S_ * DK_];     // 32 MB, layout [B,H,S,DK]
__device__ float g_k[B_ * H_ * S_ * DK_];     // 32 MB
__device__ float g_v[B_ * H_ * S_ * DK_];     // 32 MB
__device__ float g_ctx[B_ * S_ * D_];         // 32 MB, layout [B,S,D]
__device__ float g_psum[B_ * 64];             // per-block partial sums (deterministic)
__device__ float g_psq[B_ * 64];

// ---------------------------------------------------------------------------
// QKV projection: C[m, n] = sum_k X[m,k] * W[h, k, j], n = h*64 + j
// 128x128x16 tiled SGEMM, 8x8 microtile, 256 threads. z selects wq/wk/wv.
// Output written in [B,H,S,DK] layout for the attention kernel.
// ---------------------------------------------------------------------------
__global__ __launch_bounds__(256) void qkv_kernel(
    const float* __restrict__ x, const float* __restrict__ wq,
    const float* __restrict__ wk, const float* __restrict__ wv)
{
    __shared__ float As[16][132];   // A transposed, padded
    __shared__ float Bs[16][132];

    const int zi = blockIdx.z;
    const float* W = (zi == 0) ? wq : (zi == 1) ? wk : wv;
    float* out = (zi == 0) ? g_q : (zi == 1) ? g_k : g_v;

    const int n0 = blockIdx.x * 128;
    const int m0 = blockIdx.y * 128;
    const int tid = threadIdx.x;
    const int tx = tid & 15, ty = tid >> 4;

    float acc[8][8] = {};

    for (int k0 = 0; k0 < D_; k0 += 16) {
        #pragma unroll
        for (int i = 0; i < 2; i++) {          // A tile: 128 x 16
            int f = tid + i * 256;
            int r = f >> 2, c4 = (f & 3) * 4;
            float4 v = *(const float4*)(x + (m0 + r) * D_ + k0 + c4);
            As[c4 + 0][r] = v.x; As[c4 + 1][r] = v.y;
            As[c4 + 2][r] = v.z; As[c4 + 3][r] = v.w;
        }
        #pragma unroll
        for (int i = 0; i < 2; i++) {          // B tile: 16 x 128 (per-head packed)
            int f = tid + i * 256;
            int r = f >> 5, c = (f & 31) * 4;
            int n = n0 + c;
            int h = n >> 6, j = n & 63;
            *(float4*)&Bs[r][c] =
                *(const float4*)(W + h * (D_ * DK_) + (k0 + r) * DK_ + j);
        }
        __syncthreads();
        #pragma unroll
        for (int kk = 0; kk < 16; kk++) {
            float a[8], b[8];
            *(float4*)&a[0] = *(const float4*)&As[kk][ty * 8];
            *(float4*)&a[4] = *(const float4*)&As[kk][ty * 8 + 4];
            *(float4*)&b[0] = *(const float4*)&Bs[kk][tx * 8];
            *(float4*)&b[4] = *(const float4*)&Bs[kk][tx * 8 + 4];
            #pragma unroll
            for (int ii = 0; ii < 8; ii++)
                #pragma unroll
                for (int jj = 0; jj < 8; jj++)
                    acc[ii][jj] += a[ii] * b[jj];
        }
        __syncthreads();
    }

    #pragma unroll
    for (int ii = 0; ii < 8; ii++) {
        int m = m0 + ty * 8 + ii;
        int b = m >> 10, s = m & 1023;
        #pragma unroll
        for (int j4 = 0; j4 < 2; j4++) {
            int n = n0 + tx * 8 + j4 * 4;
            int h = n >> 6, j = n & 63;
            float4 v = make_float4(acc[ii][j4 * 4 + 0], acc[ii][j4 * 4 + 1],
                                   acc[ii][j4 * 4 + 2], acc[ii][j4 * 4 + 3]);
            *(float4*)(out + ((b * H_ + h) * S_ + s) * DK_ + j) = v;
        }
    }
}

// ---------------------------------------------------------------------------
// Flash attention: one block = 64 query rows of one (b,h). Online softmax over
// 16 key tiles of 64. Smem exactly 48 KB: Qs + KP (K, then reused for P; skewed
// layout to avoid 16-way LDS conflicts without padding) + Vs.
// ---------------------------------------------------------------------------
__global__ __launch_bounds__(256) void attn_kernel(const int* __restrict__ mask)
{
    __shared__ float Qs[64 * 64];
    __shared__ float KP[64 * 64];   // skewed: idx(row, col) = row*64 + ((col + row) & 63)
    __shared__ float Vs[64 * 64];

    const int bh = blockIdx.y;          // 0..127
    const int b = bh >> 4;
    const int h = bh & 15;
    const int s0 = blockIdx.x * 64;
    const int tid = threadIdx.x;
    const int tx = tid & 15, ty = tid >> 4;
    const int r0 = ty * 4;              // this thread's query rows (local)
    const int c0 = tx * 4;              // this thread's key cols / dk cols (local)

    const float* qp = g_q + (bh * S_ + s0) * DK_;
    const float* kp = g_k + bh * S_ * DK_;
    const float* vp = g_v + bh * S_ * DK_;

    #pragma unroll
    for (int i = 0; i < 4; i++) {       // load Q tile (row-major)
        int f = tid + i * 256;
        int r = f >> 4, c = (f & 15) * 4;
        *(float4*)&Qs[r * 64 + c] = *(const float4*)(qp + r * 64 + c);
    }

    float mst[4], lst[4];
    float o[4][4] = {};
    #pragma unroll
    for (int i = 0; i < 4; i++) { mst[i] = -1e30f; lst[i] = 0.f; }

    for (int t0 = 0; t0 < S_; t0 += 64) {
        __syncthreads();                // prior-iter reads of KP/Vs done
        #pragma unroll
        for (int i = 0; i < 4; i++) {   // load K (skewed) + V (row-major)
            int f = tid + i * 256;
            int r = f >> 4, c = (f & 15) * 4;
            float4 kv = *(const float4*)(kp + (t0 + r) * DK_ + c);
            KP[r * 64 + ((c + 0 + r) & 63)] = kv.x;
            KP[r * 64 + ((c + 1 + r) & 63)] = kv.y;
            KP[r * 64 + ((c + 2 + r) & 63)] = kv.z;
            KP[r * 64 + ((c + 3 + r) & 63)] = kv.w;
            *(float4*)&Vs[r * 64 + c] = *(const float4*)(vp + (t0 + r) * DK_ + c);
        }
        __syncthreads();

        // ---- scores: acc = Q * K^T ----
        float acc[4][4] = {};
        #pragma unroll 16
        for (int k = 0; k < 64; k++) {
            float qv[4], kv[4];
            #pragma unroll
            for (int i = 0; i < 4; i++) qv[i] = Qs[(r0 + i) * 64 + k];
            #pragma unroll
            for (int j = 0; j < 4; j++) kv[j] = KP[(c0 + j) * 64 + ((k + c0 + j) & 63)];
            #pragma unroll
            for (int i = 0; i < 4; i++)
                #pragma unroll
                for (int j = 0; j < 4; j++)
                    acc[i][j] += qv[i] * kv[j];
        }

        // ---- scale + mask (matches: scale first, masked -> exactly -1e9) ----
        #pragma unroll
        for (int i = 0; i < 4; i++) {
            const int4 mv = *(const int4*)(mask + (b * S_ + (s0 + r0 + i)) * S_ + t0 + c0);
            acc[i][0] = mv.x ? acc[i][0] * 0.125f : -1e9f;
            acc[i][1] = mv.y ? acc[i][1] * 0.125f : -1e9f;
            acc[i][2] = mv.z ? acc[i][2] * 0.125f : -1e9f;
            acc[i][3] = mv.w ? acc[i][3] * 0.125f : -1e9f;
        }

        // ---- online softmax (row group = 16 contiguous lanes sharing ty) ----
        float alpha[4];
        #pragma unroll
        for (int i = 0; i < 4; i++) {
            float rm = fmaxf(fmaxf(acc[i][0], acc[i][1]), fmaxf(acc[i][2], acc[i][3]));
            #pragma unroll
            for (int w = 8; w > 0; w >>= 1)
                rm = fmaxf(rm, __shfl_xor_sync(0xffffffffu, rm, w));
            float mn = fmaxf(mst[i], rm);
            alpha[i] = __expf(mst[i] - mn);
            float rs = 0.f;
            #pragma unroll
            for (int j = 0; j < 4; j++) {
                acc[i][j] = __expf(acc[i][j] - mn);
                rs += acc[i][j];
            }
            #pragma unroll
            for (int w = 8; w > 0; w >>= 1)
                rs += __shfl_xor_sync(0xffffffffu, rs, w);
            lst[i] = lst[i] * alpha[i] + rs;
            mst[i] = mn;
        }

        __syncthreads();                // everyone done reading K from KP
        #pragma unroll
        for (int i = 0; i < 4; i++) {   // rescale O; write P into KP (skewed)
            o[i][0] *= alpha[i]; o[i][1] *= alpha[i];
            o[i][2] *= alpha[i]; o[i][3] *= alpha[i];
            #pragma unroll
            for (int j = 0; j < 4; j++)
                KP[(r0 + i) * 64 + ((c0 + j + r0 + i) & 63)] = acc[i][j];
        }
        __syncthreads();

        // ---- O += P @ V ----
        #pragma unroll 8
        for (int t = 0; t < 64; t++) {
            float pv[4];
            #pragma unroll
            for (int i = 0; i < 4; i++)
                pv[i] = KP[(r0 + i) * 64 + ((t + r0 + i) & 63)];
            float4 vv = *(const float4*)&Vs[t * 64 + c0];
            #pragma unroll
            for (int i = 0; i < 4; i++) {
                o[i][0] += pv[i] * vv.x;
                o[i][1] += pv[i] * vv.y;
                o[i][2] += pv[i] * vv.z;
                o[i][3] += pv[i] * vv.w;
            }
        }
    }

    #pragma unroll
    for (int i = 0; i < 4; i++) {       // ctx[b, s, h*64 + d]
        float inv = 1.f / lst[i];
        float4 v = make_float4(o[i][0] * inv, o[i][1] * inv,
                               o[i][2] * inv, o[i][3] * inv);
        *(float4*)(g_ctx + (b * S_ + (s0 + r0 + i)) * D_ + h * DK_ + c0) = v;
    }
}

// ---------------------------------------------------------------------------
// Output projection + residual + deterministic partial LN stats.
// res = ctx @ wo + x  -> d_out;  per-block (sum, sumsq) -> g_psum/g_psq.
// ---------------------------------------------------------------------------
__global__ __launch_bounds__(256) void proj_kernel(
    const float* __restrict__ wo, const float* __restrict__ x,
    float* __restrict__ out)
{
    __shared__ float As[16][132];
    __shared__ float Bs[16][132];
    __shared__ float red[2][8];

    const int n0 = blockIdx.x * 128;
    const int m0 = blockIdx.y * 128;
    const int tid = threadIdx.x;
    const int tx = tid & 15, ty = tid >> 4;

    float acc[8][8] = {};

    for (int k0 = 0; k0 < D_; k0 += 16) {
        #pragma unroll
        for (int i = 0; i < 2; i++) {
            int f = tid + i * 256;
            int r = f >> 2, c4 = (f & 3) * 4;
            float4 v = *(const float4*)(g_ctx + (m0 + r) * D_ + k0 + c4);
            As[c4 + 0][r] = v.x; As[c4 + 1][r] = v.y;
            As[c4 + 2][r] = v.z; As[c4 + 3][r] = v.w;
        }
        #pragma unroll
        for (int i = 0; i < 2; i++) {
            int f = tid + i * 256;
            int r = f >> 5, c = (f & 31) * 4;
            *(float4*)&Bs[r][c] = *(const float4*)(wo + (k0 + r) * D_ + n0 + c);
        }
        __syncthreads();
        #pragma unroll
        for (int kk = 0; kk < 16; kk++) {
            float a[8], b[8];
            *(float4*)&a[0] = *(const float4*)&As[kk][ty * 8];
            *(float4*)&a[4] = *(const float4*)&As[kk][ty * 8 + 4];
            *(float4*)&b[0] = *(const float4*)&Bs[kk][tx * 8];
            *(float4*)&b[4] = *(const float4*)&Bs[kk][tx * 8 + 4];
            #pragma unroll
            for (int ii = 0; ii < 8; ii++)
                #pragma unroll
                for (int jj = 0; jj < 8; jj++)
                    acc[ii][jj] += a[ii] * b[jj];
        }
        __syncthreads();
    }

    float lsum = 0.f, lsq = 0.f;
    #pragma unroll
    for (int ii = 0; ii < 8; ii++) {
        int m = m0 + ty * 8 + ii;
        #pragma unroll
        for (int j4 = 0; j4 < 2; j4++) {
            int n = n0 + tx * 8 + j4 * 4;
            float4 xv = *(const float4*)(x + m * D_ + n);
            float4 v;
            v.x = acc[ii][j4 * 4 + 0] + xv.x;
            v.y = acc[ii][j4 * 4 + 1] + xv.y;
            v.z = acc[ii][j4 * 4 + 2] + xv.z;
            v.w = acc[ii][j4 * 4 + 3] + xv.w;
            lsum += v.x + v.y + v.z + v.w;
            lsq  += v.x * v.x + v.y * v.y + v.z * v.z + v.w * v.w;
            *(float4*)(out + m * D_ + n) = v;
        }
    }

    #pragma unroll
    for (int w = 16; w > 0; w >>= 1) {
        lsum += __shfl_xor_sync(0xffffffffu, lsum, w);
        lsq  += __shfl_xor_sync(0xffffffffu, lsq, w);
    }
    int warp = tid >> 5, lane = tid & 31;
    if (lane == 0) { red[0][warp] = lsum; red[1][warp] = lsq; }
    __syncthreads();
    if (tid == 0) {
        float s = 0.f, q = 0.f;
        #pragma unroll
        for (int i = 0; i < 8; i++) { s += red[0][i]; q += red[1][i]; }
        int bb = m0 >> 10;                                  // batch of this m-tile
        int part = (blockIdx.y & 7) * 8 + blockIdx.x;       // 64 parts per batch
        g_psum[bb * 64 + part] = s;
        g_psq[bb * 64 + part]  = q;
    }
}

// ---------------------------------------------------------------------------
// LayerNorm over (S, D) per batch; stats from the 64 deterministic partials.
// ---------------------------------------------------------------------------
__global__ __launch_bounds__(256) void ln_kernel(float* __restrict__ out)
{
    const int blk = blockIdx.x;      // 2048 blocks x 4096 elems; 256 per batch
    const int b = blk >> 8;
    float s = 0.f, q = 0.f;
    #pragma unroll
    for (int i = 0; i < 64; i++) { s += g_psum[b * 64 + i]; q += g_psq[b * 64 + i]; }
    const float invN = 1.f / (float)(S_ * D_);
    const float mean = s * invN;
    const float var  = q * invN - mean * mean;
    const float rstd = rsqrtf(var + 1e-5f);

    float* p = out + (size_t)blk * 4096;
    #pragma unroll
    for (int i = 0; i < 4; i++) {
        float4 v = *(float4*)(p + (threadIdx.x + i * 256) * 4);
        v.x = (v.x - mean) * rstd; v.y = (v.y - mean) * rstd;
        v.z = (v.z - mean) * rstd; v.w = (v.w - mean) * rstd;
        *(float4*)(p + (threadIdx.x + i * 256) * 4) = v;
    }
}

// ---------------------------------------------------------------------------
extern "C" void kernel_launch(void* const* d_in, const int* in_sizes, int n_in,
                              void* d_out, int out_size)
{
    (void)in_sizes; (void)n_in; (void)out_size;
    const int*   mask = (const int*)  d_in[0];
    const float* x    = (const float*)d_in[1];
    const float* wq   = (const float*)d_in[2];
    const float* wk   = (const float*)d_in[3];
    const float* wv   = (const float*)d_in[4];
    const float* wo   = (const float*)d_in[5];
    float* out = (float*)d_out;

    qkv_kernel <<<dim3(D_ / 128, M_ / 128, 3), 256>>>(x, wq, wk, wv);
    attn_kernel<<<dim3(S_ / 64, B_ * H_),      256>>>(mask);
    proj_kernel<<<dim3(D_ / 128, M_ / 128),    256>>>(wo, x, out);
    ln_kernel  <<<dim3((B_ * S_ * D_) / 4096), 256>>>(out);
}

// round 4
// speedup vs baseline: 1.0004x; 1.0004x over previous
#include <cuda_runtime.h>
#include <math.h>

#define B_  8
#define S_  1024
#define D_  1024
#define H_  16
#define DK_ 64
#define M_  (B_ * S_)   // 8192

// ---------------- scratch (static device allocations; no cudaMalloc) --------
__device__ float g_q[B_ * H_ * S_ * DK_];     // 32 MB, layout [B,H,S,DK]
__device__ float g_k[B_ * H_ * S_ * DK_];     // 32 MB
__device__ float g_v[B_ * H_ * S_ * DK_];     // 32 MB
__device__ float g_ctx[B_ * S_ * D_];         // 32 MB, layout [B,S,D]
__device__ float g_psum[B_ * 64];             // per-block partial sums (deterministic)
__device__ float g_psq[B_ * 64];

// ---------------------------------------------------------------------------
// QKV projection: C[m, n] = sum_k X[m,k] * W[h, k, j], n = h*64 + j
// 128x128x16 tiled SGEMM, 8x8 microtile, 256 threads. z selects wq/wk/wv.
// Output written in [B,H,S,DK] layout for the attention kernel.
// ---------------------------------------------------------------------------
__global__ __launch_bounds__(256) void qkv_kernel(
    const float* __restrict__ x, const float* __restrict__ wq,
    const float* __restrict__ wk, const float* __restrict__ wv)
{
    __shared__ float As[16][132];   // A transposed, padded
    __shared__ float Bs[16][132];

    const int zi = blockIdx.z;
    const float* W = (zi == 0) ? wq : (zi == 1) ? wk : wv;
    float* out = (zi == 0) ? g_q : (zi == 1) ? g_k : g_v;

    const int n0 = blockIdx.x * 128;
    const int m0 = blockIdx.y * 128;
    const int tid = threadIdx.x;
    const int tx = tid & 15, ty = tid >> 4;

    float acc[8][8] = {};

    for (int k0 = 0; k0 < D_; k0 += 16) {
        #pragma unroll
        for (int i = 0; i < 2; i++) {          // A tile: 128 x 16
            int f = tid + i * 256;
            int r = f >> 2, c4 = (f & 3) * 4;
            float4 v = *(const float4*)(x + (m0 + r) * D_ + k0 + c4);
            As[c4 + 0][r] = v.x; As[c4 + 1][r] = v.y;
            As[c4 + 2][r] = v.z; As[c4 + 3][r] = v.w;
        }
        #pragma unroll
        for (int i = 0; i < 2; i++) {          // B tile: 16 x 128 (per-head packed)
            int f = tid + i * 256;
            int r = f >> 5, c = (f & 31) * 4;
            int n = n0 + c;
            int h = n >> 6, j = n & 63;
            *(float4*)&Bs[r][c] =
                *(const float4*)(W + h * (D_ * DK_) + (k0 + r) * DK_ + j);
        }
        __syncthreads();
        #pragma unroll
        for (int kk = 0; kk < 16; kk++) {
            float a[8], b[8];
            *(float4*)&a[0] = *(const float4*)&As[kk][ty * 8];
            *(float4*)&a[4] = *(const float4*)&As[kk][ty * 8 + 4];
            *(float4*)&b[0] = *(const float4*)&Bs[kk][tx * 8];
            *(float4*)&b[4] = *(const float4*)&Bs[kk][tx * 8 + 4];
            #pragma unroll
            for (int ii = 0; ii < 8; ii++)
                #pragma unroll
                for (int jj = 0; jj < 8; jj++)
                    acc[ii][jj] += a[ii] * b[jj];
        }
        __syncthreads();
    }

    #pragma unroll
    for (int ii = 0; ii < 8; ii++) {
        int m = m0 + ty * 8 + ii;
        int b = m >> 10, s = m & 1023;
        #pragma unroll
        for (int j4 = 0; j4 < 2; j4++) {
            int n = n0 + tx * 8 + j4 * 4;
            int h = n >> 6, j = n & 63;
            float4 v = make_float4(acc[ii][j4 * 4 + 0], acc[ii][j4 * 4 + 1],
                                   acc[ii][j4 * 4 + 2], acc[ii][j4 * 4 + 3]);
            *(float4*)(out + ((b * H_ + h) * S_ + s) * DK_ + j) = v;
        }
    }
}

// ---------------------------------------------------------------------------
// Flash attention: one block = 64 query rows of one (b,h). Online softmax over
// 16 key tiles of 64. Smem exactly 48 KB: Qs + KP (K, then reused for P; skewed
// layout to avoid 16-way LDS conflicts without padding) + Vs.
// ---------------------------------------------------------------------------
__global__ __launch_bounds__(256) void attn_kernel(const int* __restrict__ mask)
{
    __shared__ float Qs[64 * 64];
    __shared__ float KP[64 * 64];   // skewed: idx(row, col) = row*64 + ((col + row) & 63)
    __shared__ float Vs[64 * 64];

    const int bh = blockIdx.y;          // 0..127
    const int b = bh >> 4;
    const int h = bh & 15;
    const int s0 = blockIdx.x * 64;
    const int tid = threadIdx.x;
    const int tx = tid & 15, ty = tid >> 4;
    const int r0 = ty * 4;              // this thread's query rows (local)
    const int c0 = tx * 4;              // this thread's key cols / dk cols (local)

    const float* qp = g_q + (bh * S_ + s0) * DK_;
    const float* kp = g_k + bh * S_ * DK_;
    const float* vp = g_v + bh * S_ * DK_;

    #pragma unroll
    for (int i = 0; i < 4; i++) {       // load Q tile (row-major)
        int f = tid + i * 256;
        int r = f >> 4, c = (f & 15) * 4;
        *(float4*)&Qs[r * 64 + c] = *(const float4*)(qp + r * 64 + c);
    }

    float mst[4], lst[4];
    float o[4][4] = {};
    #pragma unroll
    for (int i = 0; i < 4; i++) { mst[i] = -1e30f; lst[i] = 0.f; }

    for (int t0 = 0; t0 < S_; t0 += 64) {
        __syncthreads();                // prior-iter reads of KP/Vs done
        #pragma unroll
        for (int i = 0; i < 4; i++) {   // load K (skewed) + V (row-major)
            int f = tid + i * 256;
            int r = f >> 4, c = (f & 15) * 4;
            float4 kv = *(const float4*)(kp + (t0 + r) * DK_ + c);
            KP[r * 64 + ((c + 0 + r) & 63)] = kv.x;
            KP[r * 64 + ((c + 1 + r) & 63)] = kv.y;
            KP[r * 64 + ((c + 2 + r) & 63)] = kv.z;
            KP[r * 64 + ((c + 3 + r) & 63)] = kv.w;
            *(float4*)&Vs[r * 64 + c] = *(const float4*)(vp + (t0 + r) * DK_ + c);
        }
        __syncthreads();

        // ---- scores: acc = Q * K^T ----
        float acc[4][4] = {};
        #pragma unroll 16
        for (int k = 0; k < 64; k++) {
            float qv[4], kv[4];
            #pragma unroll
            for (int i = 0; i < 4; i++) qv[i] = Qs[(r0 + i) * 64 + k];
            #pragma unroll
            for (int j = 0; j < 4; j++) kv[j] = KP[(c0 + j) * 64 + ((k + c0 + j) & 63)];
            #pragma unroll
            for (int i = 0; i < 4; i++)
                #pragma unroll
                for (int j = 0; j < 4; j++)
                    acc[i][j] += qv[i] * kv[j];
        }

        // ---- scale + mask (matches: scale first, masked -> exactly -1e9) ----
        #pragma unroll
        for (int i = 0; i < 4; i++) {
            const int4 mv = *(const int4*)(mask + (b * S_ + (s0 + r0 + i)) * S_ + t0 + c0);
            acc[i][0] = mv.x ? acc[i][0] * 0.125f : -1e9f;
            acc[i][1] = mv.y ? acc[i][1] * 0.125f : -1e9f;
            acc[i][2] = mv.z ? acc[i][2] * 0.125f : -1e9f;
            acc[i][3] = mv.w ? acc[i][3] * 0.125f : -1e9f;
        }

        // ---- online softmax (row group = 16 contiguous lanes sharing ty) ----
        float alpha[4];
        #pragma unroll
        for (int i = 0; i < 4; i++) {
            float rm = fmaxf(fmaxf(acc[i][0], acc[i][1]), fmaxf(acc[i][2], acc[i][3]));
            #pragma unroll
            for (int w = 8; w > 0; w >>= 1)
                rm = fmaxf(rm, __shfl_xor_sync(0xffffffffu, rm, w));
            float mn = fmaxf(mst[i], rm);
            alpha[i] = __expf(mst[i] - mn);
            float rs = 0.f;
            #pragma unroll
            for (int j = 0; j < 4; j++) {
                acc[i][j] = __expf(acc[i][j] - mn);
                rs += acc[i][j];
            }
            #pragma unroll
            for (int w = 8; w > 0; w >>= 1)
                rs += __shfl_xor_sync(0xffffffffu, rs, w);
            lst[i] = lst[i] * alpha[i] + rs;
            mst[i] = mn;
        }

        __syncthreads();                // everyone done reading K from KP
        #pragma unroll
        for (int i = 0; i < 4; i++) {   // rescale O; write P into KP (skewed)
            o[i][0] *= alpha[i]; o[i][1] *= alpha[i];
            o[i][2] *= alpha[i]; o[i][3] *= alpha[i];
            #pragma unroll
            for (int j = 0; j < 4; j++)
                KP[(r0 + i) * 64 + ((c0 + j + r0 + i) & 63)] = acc[i][j];
        }
        __syncthreads();

        // ---- O += P @ V ----
        #pragma unroll 8
        for (int t = 0; t < 64; t++) {
            float pv[4];
            #pragma unroll
            for (int i = 0; i < 4; i++)
                pv[i] = KP[(r0 + i) * 64 + ((t + r0 + i) & 63)];
            float4 vv = *(const float4*)&Vs[t * 64 + c0];
            #pragma unroll
            for (int i = 0; i < 4; i++) {
                o[i][0] += pv[i] * vv.x;
                o[i][1] += pv[i] * vv.y;
                o[i][2] += pv[i] * vv.z;
                o[i][3] += pv[i] * vv.w;
            }
        }
    }

    #pragma unroll
    for (int i = 0; i < 4; i++) {       // ctx[b, s, h*64 + d]
        float inv = 1.f / lst[i];
        float4 v = make_float4(o[i][0] * inv, o[i][1] * inv,
                               o[i][2] * inv, o[i][3] * inv);
        *(float4*)(g_ctx + (b * S_ + (s0 + r0 + i)) * D_ + h * DK_ + c0) = v;
    }
}

// ---------------------------------------------------------------------------
// Output projection + residual + deterministic partial LN stats.
// res = ctx @ wo + x  -> d_out;  per-block (sum, sumsq) -> g_psum/g_psq.
// ---------------------------------------------------------------------------
__global__ __launch_bounds__(256) void proj_kernel(
    const float* __restrict__ wo, const float* __restrict__ x,
    float* __restrict__ out)
{
    __shared__ float As[16][132];
    __shared__ float Bs[16][132];
    __shared__ float red[2][8];

    const int n0 = blockIdx.x * 128;
    const int m0 = blockIdx.y * 128;
    const int tid = threadIdx.x;
    const int tx = tid & 15, ty = tid >> 4;

    float acc[8][8] = {};

    for (int k0 = 0; k0 < D_; k0 += 16) {
        #pragma unroll
        for (int i = 0; i < 2; i++) {
            int f = tid + i * 256;
            int r = f >> 2, c4 = (f & 3) * 4;
            float4 v = *(const float4*)(g_ctx + (m0 + r) * D_ + k0 + c4);
            As[c4 + 0][r] = v.x; As[c4 + 1][r] = v.y;
            As[c4 + 2][r] = v.z; As[c4 + 3][r] = v.w;
        }
        #pragma unroll
        for (int i = 0; i < 2; i++) {
            int f = tid + i * 256;
            int r = f >> 5, c = (f & 31) * 4;
            *(float4*)&Bs[r][c] = *(const float4*)(wo + (k0 + r) * D_ + n0 + c);
        }
        __syncthreads();
        #pragma unroll
        for (int kk = 0; kk < 16; kk++) {
            float a[8], b[8];
            *(float4*)&a[0] = *(const float4*)&As[kk][ty * 8];
            *(float4*)&a[4] = *(const float4*)&As[kk][ty * 8 + 4];
            *(float4*)&b[0] = *(const float4*)&Bs[kk][tx * 8];
            *(float4*)&b[4] = *(const float4*)&Bs[kk][tx * 8 + 4];
            #pragma unroll
            for (int ii = 0; ii < 8; ii++)
                #pragma unroll
                for (int jj = 0; jj < 8; jj++)
                    acc[ii][jj] += a[ii] * b[jj];
        }
        __syncthreads();
    }

    float lsum = 0.f, lsq = 0.f;
    #pragma unroll
    for (int ii = 0; ii < 8; ii++) {
        int m = m0 + ty * 8 + ii;
        #pragma unroll
        for (int j4 = 0; j4 < 2; j4++) {
            int n = n0 + tx * 8 + j4 * 4;
            float4 xv = *(const float4*)(x + m * D_ + n);
            float4 v;
            v.x = acc[ii][j4 * 4 + 0] + xv.x;
            v.y = acc[ii][j4 * 4 + 1] + xv.y;
            v.z = acc[ii][j4 * 4 + 2] + xv.z;
            v.w = acc[ii][j4 * 4 + 3] + xv.w;
            lsum += v.x + v.y + v.z + v.w;
            lsq  += v.x * v.x + v.y * v.y + v.z * v.z + v.w * v.w;
            *(float4*)(out + m * D_ + n) = v;
        }
    }

    #pragma unroll
    for (int w = 16; w > 0; w >>= 1) {
        lsum += __shfl_xor_sync(0xffffffffu, lsum, w);
        lsq  += __shfl_xor_sync(0xffffffffu, lsq, w);
    }
    int warp = tid >> 5, lane = tid & 31;
    if (lane == 0) { red[0][warp] = lsum; red[1][warp] = lsq; }
    __syncthreads();
    if (tid == 0) {
        float s = 0.f, q = 0.f;
        #pragma unroll
        for (int i = 0; i < 8; i++) { s += red[0][i]; q += red[1][i]; }
        int bb = m0 >> 10;                                  // batch of this m-tile
        int part = (blockIdx.y & 7) * 8 + blockIdx.x;       // 64 parts per batch
        g_psum[bb * 64 + part] = s;
        g_psq[bb * 64 + part]  = q;
    }
}

// ---------------------------------------------------------------------------
// LayerNorm over (S, D) per batch; stats from the 64 deterministic partials.
// ---------------------------------------------------------------------------
__global__ __launch_bounds__(256) void ln_kernel(float* __restrict__ out)
{
    const int blk = blockIdx.x;      // 2048 blocks x 4096 elems; 256 per batch
    const int b = blk >> 8;
    float s = 0.f, q = 0.f;
    #pragma unroll
    for (int i = 0; i < 64; i++) { s += g_psum[b * 64 + i]; q += g_psq[b * 64 + i]; }
    const float invN = 1.f / (float)(S_ * D_);
    const float mean = s * invN;
    const float var  = q * invN - mean * mean;
    const float rstd = rsqrtf(var + 1e-5f);

    float* p = out + (size_t)blk * 4096;
    #pragma unroll
    for (int i = 0; i < 4; i++) {
        float4 v = *(float4*)(p + (threadIdx.x + i * 256) * 4);
        v.x = (v.x - mean) * rstd; v.y = (v.y - mean) * rstd;
        v.z = (v.z - mean) * rstd; v.w = (v.w - mean) * rstd;
        *(float4*)(p + (threadIdx.x + i * 256) * 4) = v;
    }
}

// ---------------------------------------------------------------------------
extern "C" void kernel_launch(void* const* d_in, const int* in_sizes, int n_in,
                              void* d_out, int out_size)
{
    (void)in_sizes; (void)n_in; (void)out_size;
    const int*   mask = (const int*)  d_in[0];
    const float* x    = (const float*)d_in[1];
    const float* wq   = (const float*)d_in[2];
    const float* wk   = (const float*)d_in[3];
    const float* wv   = (const float*)d_in[4];
    const float* wo   = (const float*)d_in[5];
    float* out = (float*)d_out;

    qkv_kernel <<<dim3(D_ / 128, M_ / 128, 3), 256>>>(x, wq, wk, wv);
    attn_kernel<<<dim3(S_ / 64, B_ * H_),      256>>>(mask);
    proj_kernel<<<dim3(D_ / 128, M_ / 128),    256>>>(wo, x, out);
    ln_kernel  <<<dim3((B_ * S_ * D_) / 4096), 256>>>(out);
}

// round 5
// speedup vs baseline: 1.3534x; 1.3529x over previous
#include <cuda_runtime.h>
#include <cuda_bf16.h>
#include <math.h>
#include <stdint.h>

#define B_  8
#define S_  1024
#define D_  1024
#define H_  16
#define DK_ 64
#define M_  (B_ * S_)   // 8192
#define K3  3072        // split-K: [hi | lo | hi]

// ---------------- scratch (static device allocations; no cudaMalloc) --------
__device__ float g_q[B_ * H_ * S_ * DK_];     // [B,H,S,DK] fp32
__device__ float g_k[B_ * H_ * S_ * DK_];
__device__ float g_v[B_ * H_ * S_ * DK_];
__device__ float g_ctx[B_ * S_ * D_];         // [B,S,D] fp32
__device__ float g_psum[B_ * 64];
__device__ float g_psq[B_ * 64];

__device__ __nv_bfloat16 g_xb[M_ * K3];       // x packed   [Ah|Al|Ah]  48MB
__device__ __nv_bfloat16 g_cb[M_ * K3];       // ctx packed [Ah|Al|Ah]  48MB
__device__ __nv_bfloat16 g_wt[4 * D_ * K3];   // W^T packed [Bh|Bh|Bl] per z (q,k,v,o)

// ---------------------------------------------------------------------------
// helpers
// ---------------------------------------------------------------------------
__device__ __forceinline__ uint32_t smem_u32(const void* p) {
    return (uint32_t)__cvta_generic_to_shared(p);
}
__device__ __forceinline__ void cp16(uint32_t dst, const void* src) {
    asm volatile("cp.async.cg.shared.global [%0], [%1], 16;\n" :: "r"(dst), "l"(src));
}
__device__ __forceinline__ void ldm_x4(uint32_t addr, uint32_t& r0, uint32_t& r1,
                                       uint32_t& r2, uint32_t& r3) {
    asm volatile("ldmatrix.sync.aligned.m8n8.x4.shared.b16 {%0,%1,%2,%3}, [%4];"
                 : "=r"(r0), "=r"(r1), "=r"(r2), "=r"(r3) : "r"(addr));
}
__device__ __forceinline__ void mma_bf16(float* c, const uint32_t* a,
                                         uint32_t b0, uint32_t b1) {
    asm volatile("mma.sync.aligned.m16n8k16.row.col.f32.bf16.bf16.f32 "
                 "{%0,%1,%2,%3},{%4,%5,%6,%7},{%8,%9},{%0,%1,%2,%3};"
                 : "+f"(c[0]), "+f"(c[1]), "+f"(c[2]), "+f"(c[3])
                 : "r"(a[0]), "r"(a[1]), "r"(a[2]), "r"(a[3]), "r"(b0), "r"(b1));
}
__device__ __forceinline__ uint32_t pack2(__nv_bfloat16 a, __nv_bfloat16 b) {
    __nv_bfloat162 t(a, b);
    return *(uint32_t*)&t;
}
__device__ __forceinline__ void split_bf16(float v, __nv_bfloat16& hi, __nv_bfloat16& lo) {
    hi = __float2bfloat16(v);
    lo = __float2bfloat16(v - __bfloat162float(hi));
}

// ---------------------------------------------------------------------------
// pack A-side fp32 [M,1024] -> bf16 [M,3072] = [hi | lo | hi]
// ---------------------------------------------------------------------------
__global__ __launch_bounds__(256) void conv_a_kernel(
    const float* __restrict__ src, __nv_bfloat16* __restrict__ dst)
{
    int idx = blockIdx.x * 256 + threadIdx.x;   // one float4 per thread
    int m  = idx >> 8;
    int c4 = (idx & 255) * 4;
    float4 v = *(const float4*)(src + m * D_ + c4);
    __nv_bfloat16 h0, h1, h2, h3, l0, l1, l2, l3;
    split_bf16(v.x, h0, l0); split_bf16(v.y, h1, l1);
    split_bf16(v.z, h2, l2); split_bf16(v.w, h3, l3);
    uint2 hh = make_uint2(pack2(h0, h1), pack2(h2, h3));
    uint2 ll = make_uint2(pack2(l0, l1), pack2(l2, l3));
    __nv_bfloat16* row = dst + (size_t)m * K3 + c4;
    *(uint2*)(row)          = hh;
    *(uint2*)(row + 1024)   = ll;
    *(uint2*)(row + 2048)   = hh;
}

// ---------------------------------------------------------------------------
// pack + transpose B-side weights into g_wt[z][n][3072] = [hi | hi | lo]
// z<3: W[h,k,j] with n=h*64+j ; z==3: wo[k,n]
// ---------------------------------------------------------------------------
__global__ __launch_bounds__(256) void conv_w_kernel(
    const float* __restrict__ wq, const float* __restrict__ wk,
    const float* __restrict__ wv, const float* __restrict__ wo)
{
    __shared__ float t[32][33];
    const int z  = blockIdx.z;
    const float* W = (z == 0) ? wq : (z == 1) ? wk : (z == 2) ? wv : wo;
    const int n0 = blockIdx.x * 32;
    const int k0 = blockIdx.y * 32;
    const int tx = threadIdx.x, ty = threadIdx.y;   // (32, 8)

    #pragma unroll
    for (int i = 0; i < 4; i++) {
        int k = k0 + ty + i * 8;
        int n = n0 + tx;
        float v = (z < 3) ? W[(n >> 6) * (D_ * DK_) + k * DK_ + (n & 63)]
                          : W[k * D_ + n];
        t[ty + i * 8][tx] = v;
    }
    __syncthreads();
    __nv_bfloat16* base = g_wt + (size_t)z * D_ * K3;
    #pragma unroll
    for (int i = 0; i < 4; i++) {
        int n = n0 + ty + i * 8;
        float v = t[tx][ty + i * 8];
        __nv_bfloat16 hi, lo;
        split_bf16(v, hi, lo);
        __nv_bfloat16* row = base + (size_t)n * K3 + k0 + tx;
        row[0]    = hi;
        row[1024] = hi;
        row[2048] = lo;
    }
}

// ---------------------------------------------------------------------------
// 128x128 bf16 tensor-core GEMM core over K3=3072. 256 threads, 8 warps in
// 4(M) x 2(N); warp tile 32x64; mma m16n8k16; cp.async double buffer; smem
// rows padded to 40 elems (80B) for conflict-free ldmatrix.
// acc[mi][nj][4] per thread.
// ---------------------------------------------------------------------------
__device__ __forceinline__ void gemm_core(
    const __nv_bfloat16* __restrict__ A,
    const __nv_bfloat16* __restrict__ Bt,
    int m0, int n0, float (&acc)[2][8][4])
{
    __shared__ __align__(16) __nv_bfloat16 sA[2][128 * 40];
    __shared__ __align__(16) __nv_bfloat16 sB[2][128 * 40];

    const int tid  = threadIdx.x;
    const int lane = tid & 31;
    const int warp = tid >> 5;
    const int wm   = warp >> 1;   // 0..3
    const int wn   = warp & 1;    // 0..1

    // cp.async mapping: 2 chunks of 16B per matrix per thread
    const int lr = tid >> 2;              // 0..63
    const int lc = (tid & 3) * 8;         // element col
    const __nv_bfloat16* gA0 = A  + (size_t)(m0 + lr) * K3 + lc;
    const __nv_bfloat16* gA1 = gA0 + (size_t)64 * K3;
    const __nv_bfloat16* gB0 = Bt + (size_t)(n0 + lr) * K3 + lc;
    const __nv_bfloat16* gB1 = gB0 + (size_t)64 * K3;
    const uint32_t sA0 = smem_u32(&sA[0][lr * 40 + lc]);
    const uint32_t sA1 = sA0 + 64 * 40 * 2;
    const uint32_t sB0 = smem_u32(&sB[0][lr * 40 + lc]);
    const uint32_t sB1 = sB0 + 64 * 40 * 2;
    const uint32_t BUFB = 128 * 40 * 2;

    // ldmatrix base addresses
    const int aRow = wm * 32 + (lane & 15);
    const int aCol = (lane >> 4) * 8;
    const uint32_t aBase = smem_u32(&sA[0][0]) + (aRow * 40 + aCol) * 2;
    const int bRow = wn * 64 + (lane & 7) + ((lane >> 4) & 1) * 8;
    const int bCol = ((lane >> 3) & 1) * 8;
    const uint32_t bBase = smem_u32(&sB[0][0]) + (bRow * 40 + bCol) * 2;

    // preload stage 0
    cp16(sA0, gA0); cp16(sA1, gA1);
    cp16(sB0, gB0); cp16(sB1, gB1);
    asm volatile("cp.async.commit_group;\n" ::: "memory");

    int buf = 0;
    for (int s = 0; s < K3 / 32; s++) {
        if (s + 1 < K3 / 32) {
            const int k = (s + 1) * 32;
            const uint32_t bo = (buf ^ 1) * BUFB;
            cp16(sA0 + bo, gA0 + k); cp16(sA1 + bo, gA1 + k);
            cp16(sB0 + bo, gB0 + k); cp16(sB1 + bo, gB1 + k);
            asm volatile("cp.async.commit_group;\n" ::: "memory");
            asm volatile("cp.async.wait_group 1;\n" ::: "memory");
        } else {
            asm volatile("cp.async.wait_group 0;\n" ::: "memory");
        }
        __syncthreads();

        const uint32_t aB = aBase + buf * BUFB;
        const uint32_t bB = bBase + buf * BUFB;
        #pragma unroll
        for (int kk = 0; kk < 2; kk++) {
            uint32_t a0[4], a1[4];
            ldm_x4(aB + kk * 32,                a0[0], a0[1], a0[2], a0[3]);
            ldm_x4(aB + 16 * 80 + kk * 32,      a1[0], a1[1], a1[2], a1[3]);
            #pragma unroll
            for (int nq = 0; nq < 4; nq++) {
                uint32_t b0, b1, b2, b3;
                ldm_x4(bB + nq * 16 * 80 + kk * 32, b0, b1, b2, b3);
                mma_bf16(acc[0][2 * nq],     a0, b0, b1);
                mma_bf16(acc[0][2 * nq + 1], a0, b2, b3);
                mma_bf16(acc[1][2 * nq],     a1, b0, b1);
                mma_bf16(acc[1][2 * nq + 1], a1, b2, b3);
            }
        }
        __syncthreads();
        buf ^= 1;
    }
}

// ---------------------------------------------------------------------------
// QKV projection via tensor cores. z selects q/k/v. Output [B,H,S,DK] fp32.
// ---------------------------------------------------------------------------
__global__ __launch_bounds__(256) void qkv_mma_kernel()
{
    const int z  = blockIdx.z;
    const int n0 = blockIdx.x * 128;
    const int m0 = blockIdx.y * 128;
    float* out = (z == 0) ? g_q : (z == 1) ? g_k : g_v;

    float acc[2][8][4] = {};
    gemm_core(g_xb, g_wt + (size_t)z * D_ * K3, m0, n0, acc);

    const int lane = threadIdx.x & 31;
    const int warp = threadIdx.x >> 5;
    const int wm = warp >> 1, wn = warp & 1;
    const int mr = m0 + wm * 32 + (lane >> 2);
    const int nc = n0 + wn * 64 + (lane & 3) * 2;

    #pragma unroll
    for (int mi = 0; mi < 2; mi++) {
        #pragma unroll
        for (int nj = 0; nj < 8; nj++) {
            int n = nc + nj * 8;
            int h = n >> 6, j = n & 63;
            int m  = mr + mi * 16;
            int b  = m >> 10, ss = m & 1023;
            float* p = out + (((size_t)(b * H_ + h) * S_ + ss) * DK_ + j);
            *(float2*)p = make_float2(acc[mi][nj][0], acc[mi][nj][1]);
            int m2 = m + 8;
            int b2 = m2 >> 10, ss2 = m2 & 1023;
            float* p2 = out + (((size_t)(b2 * H_ + h) * S_ + ss2) * DK_ + j);
            *(float2*)p2 = make_float2(acc[mi][nj][2], acc[mi][nj][3]);
        }
    }
}

// ---------------------------------------------------------------------------
// Out-proj via tensor cores: out = ctx @ wo + x ; deterministic LN partials.
// ---------------------------------------------------------------------------
__global__ __launch_bounds__(256) void proj_mma_kernel(
    const float* __restrict__ x, float* __restrict__ out)
{
    __shared__ float red[2][8];
    const int n0 = blockIdx.x * 128;
    const int m0 = blockIdx.y * 128;

    float acc[2][8][4] = {};
    gemm_core(g_cb, g_wt + (size_t)3 * D_ * K3, m0, n0, acc);

    const int tid  = threadIdx.x;
    const int lane = tid & 31;
    const int warp = tid >> 5;
    const int wm = warp >> 1, wn = warp & 1;
    const int mr = m0 + wm * 32 + (lane >> 2);
    const int nc = n0 + wn * 64 + (lane & 3) * 2;

    float lsum = 0.f, lsq = 0.f;
    #pragma unroll
    for (int mi = 0; mi < 2; mi++) {
        #pragma unroll
        for (int nj = 0; nj < 8; nj++) {
            int n = nc + nj * 8;
            #pragma unroll
            for (int half = 0; half < 2; half++) {
                int m = mr + mi * 16 + half * 8;
                float v0 = acc[mi][nj][2 * half]     + x[(size_t)m * D_ + n];
                float v1 = acc[mi][nj][2 * half + 1] + x[(size_t)m * D_ + n + 1];
                lsum += v0 + v1;
                lsq  += v0 * v0 + v1 * v1;
                *(float2*)(out + (size_t)m * D_ + n) = make_float2(v0, v1);
            }
        }
    }

    #pragma unroll
    for (int w = 16; w > 0; w >>= 1) {
        lsum += __shfl_xor_sync(0xffffffffu, lsum, w);
        lsq  += __shfl_xor_sync(0xffffffffu, lsq, w);
    }
    if (lane == 0) { red[0][warp] = lsum; red[1][warp] = lsq; }
    __syncthreads();
    if (tid == 0) {
        float s = 0.f, q = 0.f;
        #pragma unroll
        for (int i = 0; i < 8; i++) { s += red[0][i]; q += red[1][i]; }
        int bb = m0 >> 10;
        int part = (blockIdx.y & 7) * 8 + blockIdx.x;
        g_psum[bb * 64 + part] = s;
        g_psq[bb * 64 + part]  = q;
    }
}

// ---------------------------------------------------------------------------
// Flash attention (fp32 SIMT, unchanged from passing R1 kernel).
// ---------------------------------------------------------------------------
__global__ __launch_bounds__(256) void attn_kernel(const int* __restrict__ mask)
{
    __shared__ float Qs[64 * 64];
    __shared__ float KP[64 * 64];
    __shared__ float Vs[64 * 64];

    const int bh = blockIdx.y;
    const int b = bh >> 4;
    const int s0 = blockIdx.x * 64;
    const int tid = threadIdx.x;
    const int tx = tid & 15, ty = tid >> 4;
    const int r0 = ty * 4;
    const int c0 = tx * 4;

    const float* qp = g_q + (bh * S_ + s0) * DK_;
    const float* kp = g_k + bh * S_ * DK_;
    const float* vp = g_v + bh * S_ * DK_;

    #pragma unroll
    for (int i = 0; i < 4; i++) {
        int f = tid + i * 256;
        int r = f >> 4, c = (f & 15) * 4;
        *(float4*)&Qs[r * 64 + c] = *(const float4*)(qp + r * 64 + c);
    }

    float mst[4], lst[4];
    float o[4][4] = {};
    #pragma unroll
    for (int i = 0; i < 4; i++) { mst[i] = -1e30f; lst[i] = 0.f; }

    for (int t0 = 0; t0 < S_; t0 += 64) {
        __syncthreads();
        #pragma unroll
        for (int i = 0; i < 4; i++) {
            int f = tid + i * 256;
            int r = f >> 4, c = (f & 15) * 4;
            float4 kv = *(const float4*)(kp + (t0 + r) * DK_ + c);
            KP[r * 64 + ((c + 0 + r) & 63)] = kv.x;
            KP[r * 64 + ((c + 1 + r) & 63)] = kv.y;
            KP[r * 64 + ((c + 2 + r) & 63)] = kv.z;
            KP[r * 64 + ((c + 3 + r) & 63)] = kv.w;
            *(float4*)&Vs[r * 64 + c] = *(const float4*)(vp + (t0 + r) * DK_ + c);
        }
        __syncthreads();

        float acc[4][4] = {};
        #pragma unroll 16
        for (int k = 0; k < 64; k++) {
            float qv[4], kv[4];
            #pragma unroll
            for (int i = 0; i < 4; i++) qv[i] = Qs[(r0 + i) * 64 + k];
            #pragma unroll
            for (int j = 0; j < 4; j++) kv[j] = KP[(c0 + j) * 64 + ((k + c0 + j) & 63)];
            #pragma unroll
            for (int i = 0; i < 4; i++)
                #pragma unroll
                for (int j = 0; j < 4; j++)
                    acc[i][j] += qv[i] * kv[j];
        }

        #pragma unroll
        for (int i = 0; i < 4; i++) {
            const int4 mv = *(const int4*)(mask + (b * S_ + (s0 + r0 + i)) * S_ + t0 + c0);
            acc[i][0] = mv.x ? acc[i][0] * 0.125f : -1e9f;
            acc[i][1] = mv.y ? acc[i][1] * 0.125f : -1e9f;
            acc[i][2] = mv.z ? acc[i][2] * 0.125f : -1e9f;
            acc[i][3] = mv.w ? acc[i][3] * 0.125f : -1e9f;
        }

        float alpha[4];
        #pragma unroll
        for (int i = 0; i < 4; i++) {
            float rm = fmaxf(fmaxf(acc[i][0], acc[i][1]), fmaxf(acc[i][2], acc[i][3]));
            #pragma unroll
            for (int w = 8; w > 0; w >>= 1)
                rm = fmaxf(rm, __shfl_xor_sync(0xffffffffu, rm, w));
            float mn = fmaxf(mst[i], rm);
            alpha[i] = __expf(mst[i] - mn);
            float rs = 0.f;
            #pragma unroll
            for (int j = 0; j < 4; j++) {
                acc[i][j] = __expf(acc[i][j] - mn);
                rs += acc[i][j];
            }
            #pragma unroll
            for (int w = 8; w > 0; w >>= 1)
                rs += __shfl_xor_sync(0xffffffffu, rs, w);
            lst[i] = lst[i] * alpha[i] + rs;
            mst[i] = mn;
        }

        __syncthreads();
        #pragma unroll
        for (int i = 0; i < 4; i++) {
            o[i][0] *= alpha[i]; o[i][1] *= alpha[i];
            o[i][2] *= alpha[i]; o[i][3] *= alpha[i];
            #pragma unroll
            for (int j = 0; j < 4; j++)
                KP[(r0 + i) * 64 + ((c0 + j + r0 + i) & 63)] = acc[i][j];
        }
        __syncthreads();

        #pragma unroll 8
        for (int t = 0; t < 64; t++) {
            float pv[4];
            #pragma unroll
            for (int i = 0; i < 4; i++)
                pv[i] = KP[(r0 + i) * 64 + ((t + r0 + i) & 63)];
            float4 vv = *(const float4*)&Vs[t * 64 + c0];
            #pragma unroll
            for (int i = 0; i < 4; i++) {
                o[i][0] += pv[i] * vv.x;
                o[i][1] += pv[i] * vv.y;
                o[i][2] += pv[i] * vv.z;
                o[i][3] += pv[i] * vv.w;
            }
        }
    }

    const int h = bh & 15;
    #pragma unroll
    for (int i = 0; i < 4; i++) {
        float inv = 1.f / lst[i];
        float4 v = make_float4(o[i][0] * inv, o[i][1] * inv,
                               o[i][2] * inv, o[i][3] * inv);
        *(float4*)(g_ctx + (b * S_ + (s0 + r0 + i)) * D_ + h * DK_ + c0) = v;
    }
}

// ---------------------------------------------------------------------------
// LayerNorm over (S, D) per batch from the 64 deterministic partials.
// ---------------------------------------------------------------------------
__global__ __launch_bounds__(256) void ln_kernel(float* __restrict__ out)
{
    const int blk = blockIdx.x;
    const int b = blk >> 8;
    float s = 0.f, q = 0.f;
    #pragma unroll
    for (int i = 0; i < 64; i++) { s += g_psum[b * 64 + i]; q += g_psq[b * 64 + i]; }
    const float invN = 1.f / (float)(S_ * D_);
    const float mean = s * invN;
    const float var  = q * invN - mean * mean;
    const float rstd = rsqrtf(var + 1e-5f);

    float* p = out + (size_t)blk * 4096;
    #pragma unroll
    for (int i = 0; i < 4; i++) {
        float4 v = *(float4*)(p + (threadIdx.x + i * 256) * 4);
        v.x = (v.x - mean) * rstd; v.y = (v.y - mean) * rstd;
        v.z = (v.z - mean) * rstd; v.w = (v.w - mean) * rstd;
        *(float4*)(p + (threadIdx.x + i * 256) * 4) = v;
    }
}

// ---------------------------------------------------------------------------
extern "C" void kernel_launch(void* const* d_in, const int* in_sizes, int n_in,
                              void* d_out, int out_size)
{
    (void)in_sizes; (void)n_in; (void)out_size;
    const int*   mask = (const int*)  d_in[0];
    const float* x    = (const float*)d_in[1];
    const float* wq   = (const float*)d_in[2];
    const float* wk   = (const float*)d_in[3];
    const float* wv   = (const float*)d_in[4];
    const float* wo   = (const float*)d_in[5];
    float* out = (float*)d_out;

    __nv_bfloat16* xb;  cudaGetSymbolAddress((void**)&xb,  g_xb);
    __nv_bfloat16* cb;  cudaGetSymbolAddress((void**)&cb,  g_cb);
    float* ctx;         cudaGetSymbolAddress((void**)&ctx, g_ctx);

    conv_a_kernel<<<M_ * (D_ / 1024), 256>>>(x, xb);               // 8192 blocks
    conv_w_kernel<<<dim3(32, 32, 4), dim3(32, 8)>>>(wq, wk, wv, wo);
    qkv_mma_kernel<<<dim3(D_ / 128, M_ / 128, 3), 256>>>();
    attn_kernel<<<dim3(S_ / 64, B_ * H_), 256>>>(mask);
    conv_a_kernel<<<M_ * (D_ / 1024), 256>>>(ctx, cb);
    proj_mma_kernel<<<dim3(D_ / 128, M_ / 128), 256>>>(x, out);
    ln_kernel<<<(B_ * S_ * D_) / 4096, 256>>>(out);
}

// round 6
// speedup vs baseline: 2.4826x; 1.8343x over previous
#include <cuda_runtime.h>
#include <cuda_bf16.h>
#include <math.h>
#include <stdint.h>

#define B_  8
#define S_  1024
#define D_  1024
#define H_  16
#define DK_ 64
#define M_  (B_ * S_)   // 8192
#define K3  3072        // split-K: [hi | lo | hi]

#define QT  128         // attention: query rows per block
#define KT  64          // attention: keys per tile
#define PAD 72          // smem row stride (bf16 elems) -> conflict-free ldmatrix
#define MW  (S_ / 32)   // mask words per row

// ---------------- scratch (static device allocations; no cudaMalloc) --------
__device__ __nv_bfloat16 g_qh[B_ * H_ * S_ * DK_];   // pre-split bf16 Q/K/V
__device__ __nv_bfloat16 g_ql[B_ * H_ * S_ * DK_];
__device__ __nv_bfloat16 g_kh[B_ * H_ * S_ * DK_];
__device__ __nv_bfloat16 g_kl[B_ * H_ * S_ * DK_];
__device__ __nv_bfloat16 g_vh[B_ * H_ * S_ * DK_];
__device__ __nv_bfloat16 g_vl[B_ * H_ * S_ * DK_];
__device__ float g_ctx[B_ * S_ * D_];                // [B,S,D] fp32
__device__ float g_psum[B_ * 64];
__device__ float g_psq[B_ * 64];
__device__ uint32_t g_mbits[B_ * S_ * MW];           // packed mask bits (1MB)

__device__ __nv_bfloat16 g_xb[M_ * K3];              // x packed   [Ah|Al|Ah]
__device__ __nv_bfloat16 g_cb[M_ * K3];              // ctx packed [Ah|Al|Ah]
__device__ __nv_bfloat16 g_wt[4 * D_ * K3];          // W^T packed [Bh|Bh|Bl]

// ---------------------------------------------------------------------------
// helpers
// ---------------------------------------------------------------------------
__device__ __forceinline__ uint32_t smem_u32(const void* p) {
    return (uint32_t)__cvta_generic_to_shared(p);
}
__device__ __forceinline__ void cp16(uint32_t dst, const void* src) {
    asm volatile("cp.async.cg.shared.global [%0], [%1], 16;\n" :: "r"(dst), "l"(src));
}
__device__ __forceinline__ void ldm_x4(uint32_t addr, uint32_t& r0, uint32_t& r1,
                                       uint32_t& r2, uint32_t& r3) {
    asm volatile("ldmatrix.sync.aligned.m8n8.x4.shared.b16 {%0,%1,%2,%3}, [%4];"
                 : "=r"(r0), "=r"(r1), "=r"(r2), "=r"(r3) : "r"(addr));
}
__device__ __forceinline__ void ldm_x4t(uint32_t addr, uint32_t& r0, uint32_t& r1,
                                        uint32_t& r2, uint32_t& r3) {
    asm volatile("ldmatrix.sync.aligned.m8n8.x4.trans.shared.b16 {%0,%1,%2,%3}, [%4];"
                 : "=r"(r0), "=r"(r1), "=r"(r2), "=r"(r3) : "r"(addr));
}
__device__ __forceinline__ void mma_bf16(float* c, const uint32_t* a,
                                         uint32_t b0, uint32_t b1) {
    asm volatile("mma.sync.aligned.m16n8k16.row.col.f32.bf16.bf16.f32 "
                 "{%0,%1,%2,%3},{%4,%5,%6,%7},{%8,%9},{%0,%1,%2,%3};"
                 : "+f"(c[0]), "+f"(c[1]), "+f"(c[2]), "+f"(c[3])
                 : "r"(a[0]), "r"(a[1]), "r"(a[2]), "r"(a[3]), "r"(b0), "r"(b1));
}
__device__ __forceinline__ uint32_t pack2(__nv_bfloat16 a, __nv_bfloat16 b) {
    __nv_bfloat162 t(a, b);
    return *(uint32_t*)&t;
}
__device__ __forceinline__ void split_bf16(float v, __nv_bfloat16& hi, __nv_bfloat16& lo) {
    hi = __float2bfloat16(v);
    lo = __float2bfloat16(v - __bfloat162float(hi));
}
__device__ __forceinline__ void packhl(float x, float y, uint32_t& hi, uint32_t& lo) {
    __nv_bfloat16 hx, lx, hy, ly;
    split_bf16(x, hx, lx); split_bf16(y, hy, ly);
    hi = pack2(hx, hy); lo = pack2(lx, ly);
}

// ---------------------------------------------------------------------------
// pack A-side fp32 [M,1024] -> bf16 [M,3072] = [hi | lo | hi]
// ---------------------------------------------------------------------------
__global__ __launch_bounds__(256) void conv_a_kernel(
    const float* __restrict__ src, __nv_bfloat16* __restrict__ dst)
{
    int idx = blockIdx.x * 256 + threadIdx.x;
    int m  = idx >> 8;
    int c4 = (idx & 255) * 4;
    float4 v = *(const float4*)(src + m * D_ + c4);
    __nv_bfloat16 h0, h1, h2, h3, l0, l1, l2, l3;
    split_bf16(v.x, h0, l0); split_bf16(v.y, h1, l1);
    split_bf16(v.z, h2, l2); split_bf16(v.w, h3, l3);
    uint2 hh = make_uint2(pack2(h0, h1), pack2(h2, h3));
    uint2 ll = make_uint2(pack2(l0, l1), pack2(l2, l3));
    __nv_bfloat16* row = dst + (size_t)m * K3 + c4;
    *(uint2*)(row)        = hh;
    *(uint2*)(row + 1024) = ll;
    *(uint2*)(row + 2048) = hh;
}

// ---------------------------------------------------------------------------
// pack + transpose B-side weights into g_wt[z][n][3072] = [hi | hi | lo]
// ---------------------------------------------------------------------------
__global__ __launch_bounds__(256) void conv_w_kernel(
    const float* __restrict__ wq, const float* __restrict__ wk,
    const float* __restrict__ wv, const float* __restrict__ wo)
{
    __shared__ float t[32][33];
    const int z  = blockIdx.z;
    const float* W = (z == 0) ? wq : (z == 1) ? wk : (z == 2) ? wv : wo;
    const int n0 = blockIdx.x * 32;
    const int k0 = blockIdx.y * 32;
    const int tx = threadIdx.x, ty = threadIdx.y;

    #pragma unroll
    for (int i = 0; i < 4; i++) {
        int k = k0 + ty + i * 8;
        int n = n0 + tx;
        float v = (z < 3) ? W[(n >> 6) * (D_ * DK_) + k * DK_ + (n & 63)]
                          : W[k * D_ + n];
        t[ty + i * 8][tx] = v;
    }
    __syncthreads();
    __nv_bfloat16* base = g_wt + (size_t)z * D_ * K3;
    #pragma unroll
    for (int i = 0; i < 4; i++) {
        int n = n0 + ty + i * 8;
        float v = t[tx][ty + i * 8];
        __nv_bfloat16 hi, lo;
        split_bf16(v, hi, lo);
        __nv_bfloat16* row = base + (size_t)n * K3 + k0 + tx;
        row[0]    = hi;
        row[1024] = hi;
        row[2048] = lo;
    }
}

// ---------------------------------------------------------------------------
// pack mask -> bits: g_mbits[b][s][t/32], bit t = (mask != 0)
// ---------------------------------------------------------------------------
__global__ __launch_bounds__(256) void mask_pack_kernel(const int* __restrict__ mask)
{
    int w = blockIdx.x * 8 + (threadIdx.x >> 5);
    int lane = threadIdx.x & 31;
    int v = mask[(size_t)w * 32 + lane];
    uint32_t bits = __ballot_sync(0xffffffffu, v != 0);
    if (lane == 0) g_mbits[w] = bits;
}

// ---------------------------------------------------------------------------
// 128x128 bf16 tensor-core GEMM core over K3=3072 (unchanged from R5).
// ---------------------------------------------------------------------------
__device__ __forceinline__ void gemm_core(
    const __nv_bfloat16* __restrict__ A,
    const __nv_bfloat16* __restrict__ Bt,
    int m0, int n0, float (&acc)[2][8][4])
{
    __shared__ __align__(16) __nv_bfloat16 sA[2][128 * 40];
    __shared__ __align__(16) __nv_bfloat16 sB[2][128 * 40];

    const int tid  = threadIdx.x;
    const int lane = tid & 31;
    const int warp = tid >> 5;
    const int wm   = warp >> 1;
    const int wn   = warp & 1;

    const int lr = tid >> 2;
    const int lc = (tid & 3) * 8;
    const __nv_bfloat16* gA0 = A  + (size_t)(m0 + lr) * K3 + lc;
    const __nv_bfloat16* gA1 = gA0 + (size_t)64 * K3;
    const __nv_bfloat16* gB0 = Bt + (size_t)(n0 + lr) * K3 + lc;
    const __nv_bfloat16* gB1 = gB0 + (size_t)64 * K3;
    const uint32_t sA0 = smem_u32(&sA[0][lr * 40 + lc]);
    const uint32_t sA1 = sA0 + 64 * 40 * 2;
    const uint32_t sB0 = smem_u32(&sB[0][lr * 40 + lc]);
    const uint32_t sB1 = sB0 + 64 * 40 * 2;
    const uint32_t BUFB = 128 * 40 * 2;

    const int aRow = wm * 32 + (lane & 15);
    const int aCol = (lane >> 4) * 8;
    const uint32_t aBase = smem_u32(&sA[0][0]) + (aRow * 40 + aCol) * 2;
    const int bRow = wn * 64 + (lane & 7) + ((lane >> 4) & 1) * 8;
    const int bCol = ((lane >> 3) & 1) * 8;
    const uint32_t bBase = smem_u32(&sB[0][0]) + (bRow * 40 + bCol) * 2;

    cp16(sA0, gA0); cp16(sA1, gA1);
    cp16(sB0, gB0); cp16(sB1, gB1);
    asm volatile("cp.async.commit_group;\n" ::: "memory");

    int buf = 0;
    for (int s = 0; s < K3 / 32; s++) {
        if (s + 1 < K3 / 32) {
            const int k = (s + 1) * 32;
            const uint32_t bo = (buf ^ 1) * BUFB;
            cp16(sA0 + bo, gA0 + k); cp16(sA1 + bo, gA1 + k);
            cp16(sB0 + bo, gB0 + k); cp16(sB1 + bo, gB1 + k);
            asm volatile("cp.async.commit_group;\n" ::: "memory");
            asm volatile("cp.async.wait_group 1;\n" ::: "memory");
        } else {
            asm volatile("cp.async.wait_group 0;\n" ::: "memory");
        }
        __syncthreads();

        const uint32_t aB = aBase + buf * BUFB;
        const uint32_t bB = bBase + buf * BUFB;
        #pragma unroll
        for (int kk = 0; kk < 2; kk++) {
            uint32_t a0[4], a1[4];
            ldm_x4(aB + kk * 32,           a0[0], a0[1], a0[2], a0[3]);
            ldm_x4(aB + 16 * 80 + kk * 32, a1[0], a1[1], a1[2], a1[3]);
            #pragma unroll
            for (int nq = 0; nq < 4; nq++) {
                uint32_t b0, b1, b2, b3;
                ldm_x4(bB + nq * 16 * 80 + kk * 32, b0, b1, b2, b3);
                mma_bf16(acc[0][2 * nq],     a0, b0, b1);
                mma_bf16(acc[0][2 * nq + 1], a0, b2, b3);
                mma_bf16(acc[1][2 * nq],     a1, b0, b1);
                mma_bf16(acc[1][2 * nq + 1], a1, b2, b3);
            }
        }
        __syncthreads();
        buf ^= 1;
    }
}

// ---------------------------------------------------------------------------
// QKV projection: epilogue writes pre-split bf16 hi/lo [B,H,S,DK].
// Q gets the 1/sqrt(DK)=0.125 scale folded in (exact, power of 2).
// ---------------------------------------------------------------------------
__global__ __launch_bounds__(256) void qkv_mma_kernel()
{
    const int z  = blockIdx.z;
    const int n0 = blockIdx.x * 128;
    const int m0 = blockIdx.y * 128;
    __nv_bfloat16* outH = (z == 0) ? g_qh : (z == 1) ? g_kh : g_vh;
    __nv_bfloat16* outL = (z == 0) ? g_ql : (z == 1) ? g_kl : g_vl;
    const float scale = (z == 0) ? 0.125f : 1.0f;

    float acc[2][8][4] = {};
    gemm_core(g_xb, g_wt + (size_t)z * D_ * K3, m0, n0, acc);

    const int lane = threadIdx.x & 31;
    const int warp = threadIdx.x >> 5;
    const int wm = warp >> 1, wn = warp & 1;
    const int mr = m0 + wm * 32 + (lane >> 2);
    const int nc = n0 + wn * 64 + (lane & 3) * 2;

    #pragma unroll
    for (int mi = 0; mi < 2; mi++) {
        #pragma unroll
        for (int nj = 0; nj < 8; nj++) {
            int n = nc + nj * 8;
            int h = n >> 6, j = n & 63;
            #pragma unroll
            for (int half = 0; half < 2; half++) {
                int m = mr + mi * 16 + half * 8;
                int b = m >> 10, ss = m & 1023;
                float v0 = acc[mi][nj][2 * half]     * scale;
                float v1 = acc[mi][nj][2 * half + 1] * scale;
                uint32_t hi, lo;
                packhl(v0, v1, hi, lo);
                size_t idx = ((size_t)(b * H_ + h) * S_ + ss) * DK_ + j;
                *(uint32_t*)(outH + idx) = hi;
                *(uint32_t*)(outL + idx) = lo;
            }
        }
    }
}

// ---------------------------------------------------------------------------
// Tensor-core flash attention. Block = 128 query rows of one (b,h), 8 warps,
// warp = 16 rows. 64-key tiles, double-buffered cp.async of Kh/Kl/Vh/Vl.
// QK^T = QhKh + QlKh + QhKl ; PV = PhVh + PlVh + PhVl. Softmax in registers.
// ---------------------------------------------------------------------------
__global__ __launch_bounds__(256, 2) void attn_tc_kernel()
{
    extern __shared__ __align__(16) __nv_bfloat16 sm[];
    __nv_bfloat16* sQ  = sm;                   // Qh [128*72] then Ql [128*72]
    __nv_bfloat16* sKV = sm + 2 * QT * PAD;    // 2 bufs x (Kh,Kl,Vh,Vl)[64*72]

    const int bh = blockIdx.y, b = bh >> 4, h = bh & 15;
    const int s0 = blockIdx.x * QT;
    const int tid = threadIdx.x, lane = tid & 31, warp = tid >> 5;

    const __nv_bfloat16* gQh = g_qh + ((size_t)bh * S_ + s0) * DK_;
    const __nv_bfloat16* gQl = g_ql + ((size_t)bh * S_ + s0) * DK_;
    const __nv_bfloat16* gKh = g_kh + (size_t)bh * S_ * DK_;
    const __nv_bfloat16* gKl = g_kl + (size_t)bh * S_ * DK_;
    const __nv_bfloat16* gVh = g_vh + (size_t)bh * S_ * DK_;
    const __nv_bfloat16* gVl = g_vl + (size_t)bh * S_ * DK_;

    // Q tiles -> smem (hi, lo)
    #pragma unroll
    for (int i = 0; i < 4; i++) {
        int c = tid + i * 256;
        int r = c >> 3, cl = (c & 7) * 8;
        cp16(smem_u32(sQ + r * PAD + cl),            gQh + r * DK_ + cl);
        cp16(smem_u32(sQ + QT * PAD + r * PAD + cl), gQl + r * DK_ + cl);
    }
    // KV tile 0 -> buf 0
    const uint32_t smKV = smem_u32(sKV);
    const uint32_t MATB = KT * PAD * 2;        // bytes per matrix
    const uint32_t BUFB2 = 4 * MATB;           // bytes per buffer
    #pragma unroll
    for (int i = 0; i < 2; i++) {
        int c = tid + i * 256;
        int r = c >> 3, cl = (c & 7) * 8;
        uint32_t d = smKV + (uint32_t)(r * PAD + cl) * 2;
        cp16(d,            gKh + r * DK_ + cl);
        cp16(d + MATB,     gKl + r * DK_ + cl);
        cp16(d + 2 * MATB, gVh + r * DK_ + cl);
        cp16(d + 3 * MATB, gVl + r * DK_ + cl);
    }
    asm volatile("cp.async.commit_group;\n" ::: "memory");

    // ldmatrix fragment offsets
    const uint32_t smQ  = smem_u32(sQ);
    const uint32_t aOff = ((warp * 16 + (lane & 15)) * PAD + (lane >> 4) * 8) * 2;
    const uint32_t kOff = (((lane & 7) + ((lane >> 4) & 1) * 8) * PAD
                           + ((lane >> 3) & 1) * 8) * 2;
    const uint32_t vOff = (((lane & 7) + ((lane >> 3) & 1) * 8) * PAD
                           + ((lane >> 4) & 1) * 8) * 2;

    float oacc[8][4] = {};
    float mst[2] = {-1e30f, -1e30f}, lst[2] = {0.f, 0.f};

    const int r  = lane >> 2;
    const int q2 = (lane & 3) * 2;
    const uint32_t* mrow = g_mbits + ((size_t)b * S_ + s0 + warp * 16 + r) * MW;

    for (int t = 0; t < S_ / KT; t++) {
        const int buf = t & 1;
        if (t + 1 < S_ / KT) {
            const int t0n = (t + 1) * KT;
            #pragma unroll
            for (int i = 0; i < 2; i++) {
                int c = tid + i * 256;
                int rr = c >> 3, cl = (c & 7) * 8;
                uint32_t d = smKV + (buf ^ 1) * BUFB2 + (uint32_t)(rr * PAD + cl) * 2;
                cp16(d,            gKh + (t0n + rr) * DK_ + cl);
                cp16(d + MATB,     gKl + (t0n + rr) * DK_ + cl);
                cp16(d + 2 * MATB, gVh + (t0n + rr) * DK_ + cl);
                cp16(d + 3 * MATB, gVl + (t0n + rr) * DK_ + cl);
            }
            asm volatile("cp.async.commit_group;\n" ::: "memory");
            asm volatile("cp.async.wait_group 1;\n" ::: "memory");
        } else {
            asm volatile("cp.async.wait_group 0;\n" ::: "memory");
        }
        __syncthreads();

        // ---- S = Qh*Kh^T + Ql*Kh^T + Qh*Kl^T ----
        float sacc[8][4] = {};
        const uint32_t kB = smKV + buf * BUFB2 + kOff;
        #pragma unroll
        for (int kk = 0; kk < 4; kk++) {
            uint32_t ah[4], al[4];
            ldm_x4(smQ + aOff + kk * 32,                ah[0], ah[1], ah[2], ah[3]);
            ldm_x4(smQ + QT * PAD * 2 + aOff + kk * 32, al[0], al[1], al[2], al[3]);
            #pragma unroll
            for (int nt = 0; nt < 4; nt++) {
                uint32_t b0, b1, b2, b3;
                ldm_x4(kB + nt * (16 * PAD * 2) + kk * 32, b0, b1, b2, b3);
                mma_bf16(sacc[2 * nt],     ah, b0, b1);
                mma_bf16(sacc[2 * nt + 1], ah, b2, b3);
                mma_bf16(sacc[2 * nt],     al, b0, b1);
                mma_bf16(sacc[2 * nt + 1], al, b2, b3);
                uint32_t c0, c1, c2, c3;
                ldm_x4(kB + MATB + nt * (16 * PAD * 2) + kk * 32, c0, c1, c2, c3);
                mma_bf16(sacc[2 * nt],     ah, c0, c1);
                mma_bf16(sacc[2 * nt + 1], ah, c2, c3);
            }
        }

        // ---- mask (bit-packed) ----
        uint2 w0 = *(const uint2*)(mrow + (t * KT >> 5));
        uint2 w8 = *(const uint2*)(mrow + 8 * MW + (t * KT >> 5));
        #pragma unroll
        for (int nt = 0; nt < 8; nt++) {
            int c = nt * 8 + q2;                 // even, pair never straddles words
            uint32_t m0 = (c < 32) ? (w0.x >> c) : (w0.y >> (c - 32));
            uint32_t m8 = (c < 32) ? (w8.x >> c) : (w8.y >> (c - 32));
            sacc[nt][0] = (m0 & 1) ? sacc[nt][0] : -1e9f;
            sacc[nt][1] = (m0 & 2) ? sacc[nt][1] : -1e9f;
            sacc[nt][2] = (m8 & 1) ? sacc[nt][2] : -1e9f;
            sacc[nt][3] = (m8 & 2) ? sacc[nt][3] : -1e9f;
        }

        // ---- online softmax (lane-quad reductions) ----
        float alpha[2];
        #pragma unroll
        for (int hf = 0; hf < 2; hf++) {
            float mx = -1e30f;
            #pragma unroll
            for (int nt = 0; nt < 8; nt++)
                mx = fmaxf(mx, fmaxf(sacc[nt][2 * hf], sacc[nt][2 * hf + 1]));
            mx = fmaxf(mx, __shfl_xor_sync(0xffffffffu, mx, 1));
            mx = fmaxf(mx, __shfl_xor_sync(0xffffffffu, mx, 2));
            float mn = fmaxf(mst[hf], mx);
            alpha[hf] = __expf(mst[hf] - mn);
            mst[hf] = mn;
            float rs = 0.f;
            #pragma unroll
            for (int nt = 0; nt < 8; nt++) {
                float p0 = __expf(sacc[nt][2 * hf]     - mn);
                float p1 = __expf(sacc[nt][2 * hf + 1] - mn);
                sacc[nt][2 * hf] = p0; sacc[nt][2 * hf + 1] = p1;
                rs += p0 + p1;
            }
            rs += __shfl_xor_sync(0xffffffffu, rs, 1);
            rs += __shfl_xor_sync(0xffffffffu, rs, 2);
            lst[hf] = lst[hf] * alpha[hf] + rs;
        }
        #pragma unroll
        for (int nt = 0; nt < 8; nt++) {
            oacc[nt][0] *= alpha[0]; oacc[nt][1] *= alpha[0];
            oacc[nt][2] *= alpha[1]; oacc[nt][3] *= alpha[1];
        }

        // ---- O += Ph*Vh + Pl*Vh + Ph*Vl  (P from registers; V via trans ldm)
        const uint32_t vB = smKV + buf * BUFB2 + 2 * MATB + vOff;
        #pragma unroll
        for (int kk = 0; kk < 4; kk++) {
            uint32_t pa[4], pl[4];
            packhl(sacc[2 * kk][0],     sacc[2 * kk][1],     pa[0], pl[0]);
            packhl(sacc[2 * kk][2],     sacc[2 * kk][3],     pa[1], pl[1]);
            packhl(sacc[2 * kk + 1][0], sacc[2 * kk + 1][1], pa[2], pl[2]);
            packhl(sacc[2 * kk + 1][2], sacc[2 * kk + 1][3], pa[3], pl[3]);
            #pragma unroll
            for (int nt = 0; nt < 4; nt++) {
                uint32_t v0, v1, v2, v3;
                ldm_x4t(vB + kk * (16 * PAD * 2) + nt * 32, v0, v1, v2, v3);
                mma_bf16(oacc[2 * nt],     pa, v0, v1);
                mma_bf16(oacc[2 * nt + 1], pa, v2, v3);
                mma_bf16(oacc[2 * nt],     pl, v0, v1);
                mma_bf16(oacc[2 * nt + 1], pl, v2, v3);
                uint32_t u0, u1, u2, u3;
                ldm_x4t(vB + MATB + kk * (16 * PAD * 2) + nt * 32, u0, u1, u2, u3);
                mma_bf16(oacc[2 * nt],     pa, u0, u1);
                mma_bf16(oacc[2 * nt + 1], pa, u2, u3);
            }
        }
        __syncthreads();
    }

    // ---- normalize + write ctx[b, s, h*64 + dk] ----
    const float inv0 = 1.f / lst[0], inv1 = 1.f / lst[1];
    float* b0p = g_ctx + ((size_t)b * S_ + s0 + warp * 16 + r) * D_ + h * DK_;
    float* b8p = b0p + 8 * D_;
    #pragma unroll
    for (int nt = 0; nt < 8; nt++) {
        *(float2*)(b0p + nt * 8 + q2) =
            make_float2(oacc[nt][0] * inv0, oacc[nt][1] * inv0);
        *(float2*)(b8p + nt * 8 + q2) =
            make_float2(oacc[nt][2] * inv1, oacc[nt][3] * inv1);
    }
}

// ---------------------------------------------------------------------------
// Out-proj via tensor cores: out = ctx @ wo + x ; deterministic LN partials.
// ---------------------------------------------------------------------------
__global__ __launch_bounds__(256) void proj_mma_kernel(
    const float* __restrict__ x, float* __restrict__ out)
{
    __shared__ float red[2][8];
    const int n0 = blockIdx.x * 128;
    const int m0 = blockIdx.y * 128;

    float acc[2][8][4] = {};
    gemm_core(g_cb, g_wt + (size_t)3 * D_ * K3, m0, n0, acc);

    const int tid  = threadIdx.x;
    const int lane = tid & 31;
    const int warp = tid >> 5;
    const int wm = warp >> 1, wn = warp & 1;
    const int mr = m0 + wm * 32 + (lane >> 2);
    const int nc = n0 + wn * 64 + (lane & 3) * 2;

    float lsum = 0.f, lsq = 0.f;
    #pragma unroll
    for (int mi = 0; mi < 2; mi++) {
        #pragma unroll
        for (int nj = 0; nj < 8; nj++) {
            int n = nc + nj * 8;
            #pragma unroll
            for (int half = 0; half < 2; half++) {
                int m = mr + mi * 16 + half * 8;
                float v0 = acc[mi][nj][2 * half]     + x[(size_t)m * D_ + n];
                float v1 = acc[mi][nj][2 * half + 1] + x[(size_t)m * D_ + n + 1];
                lsum += v0 + v1;
                lsq  += v0 * v0 + v1 * v1;
                *(float2*)(out + (size_t)m * D_ + n) = make_float2(v0, v1);
            }
        }
    }

    #pragma unroll
    for (int w = 16; w > 0; w >>= 1) {
        lsum += __shfl_xor_sync(0xffffffffu, lsum, w);
        lsq  += __shfl_xor_sync(0xffffffffu, lsq, w);
    }
    if (lane == 0) { red[0][warp] = lsum; red[1][warp] = lsq; }
    __syncthreads();
    if (tid == 0) {
        float s = 0.f, q = 0.f;
        #pragma unroll
        for (int i = 0; i < 8; i++) { s += red[0][i]; q += red[1][i]; }
        int bb = m0 >> 10;
        int part = (blockIdx.y & 7) * 8 + blockIdx.x;
        g_psum[bb * 64 + part] = s;
        g_psq[bb * 64 + part]  = q;
    }
}

// ---------------------------------------------------------------------------
// LayerNorm over (S, D) per batch from the 64 deterministic partials.
// ---------------------------------------------------------------------------
__global__ __launch_bounds__(256) void ln_kernel(float* __restrict__ out)
{
    const int blk = blockIdx.x;
    const int b = blk >> 8;
    float s = 0.f, q = 0.f;
    #pragma unroll
    for (int i = 0; i < 64; i++) { s += g_psum[b * 64 + i]; q += g_psq[b * 64 + i]; }
    const float invN = 1.f / (float)(S_ * D_);
    const float mean = s * invN;
    const float var  = q * invN - mean * mean;
    const float rstd = rsqrtf(var + 1e-5f);

    float* p = out + (size_t)blk * 4096;
    #pragma unroll
    for (int i = 0; i < 4; i++) {
        float4 v = *(float4*)(p + (threadIdx.x + i * 256) * 4);
        v.x = (v.x - mean) * rstd; v.y = (v.y - mean) * rstd;
        v.z = (v.z - mean) * rstd; v.w = (v.w - mean) * rstd;
        *(float4*)(p + (threadIdx.x + i * 256) * 4) = v;
    }
}

// ---------------------------------------------------------------------------
extern "C" void kernel_launch(void* const* d_in, const int* in_sizes, int n_in,
                              void* d_out, int out_size)
{
    (void)in_sizes; (void)n_in; (void)out_size;
    const int*   mask = (const int*)  d_in[0];
    const float* x    = (const float*)d_in[1];
    const float* wq   = (const float*)d_in[2];
    const float* wk   = (const float*)d_in[3];
    const float* wv   = (const float*)d_in[4];
    const float* wo   = (const float*)d_in[5];
    float* out = (float*)d_out;

    __nv_bfloat16* xb;  cudaGetSymbolAddress((void**)&xb,  g_xb);
    __nv_bfloat16* cb;  cudaGetSymbolAddress((void**)&cb,  g_cb);
    float* ctx;         cudaGetSymbolAddress((void**)&ctx, g_ctx);

    const int ATTN_SMEM = (2 * QT * PAD + 8 * KT * PAD) * 2;   // 110592 B
    cudaFuncSetAttribute(attn_tc_kernel,
                         cudaFuncAttributeMaxDynamicSharedMemorySize, ATTN_SMEM);

    mask_pack_kernel<<<(B_ * S_ * MW) / 8, 256>>>(mask);
    conv_a_kernel<<<M_ * (D_ / 1024), 256>>>(x, xb);
    conv_w_kernel<<<dim3(32, 32, 4), dim3(32, 8)>>>(wq, wk, wv, wo);
    qkv_mma_kernel<<<dim3(D_ / 128, M_ / 128, 3), 256>>>();
    attn_tc_kernel<<<dim3(S_ / QT, B_ * H_), 256, ATTN_SMEM>>>();
    conv_a_kernel<<<M_ * (D_ / 1024), 256>>>(ctx, cb);
    proj_mma_kernel<<<dim3(D_ / 128, M_ / 128), 256>>>(x, out);
    ln_kernel<<<(B_ * S_ * D_) / 4096, 256>>>(out);
}

// round 8
// speedup vs baseline: 2.6631x; 1.0727x over previous
#include <cuda_runtime.h>
#include <cuda_bf16.h>
#include <math.h>
#include <stdint.h>

#define B_  8
#define S_  1024
#define D_  1024
#define H_  16
#define DK_ 64
#define M_  (B_ * S_)   // 8192
#define K3  3072        // split-K: [hi | lo | hi]

#define QT  128         // attention: query rows per block
#define KT  64          // attention: keys per tile
#define PAD 72          // attn smem row stride
#define MW  (S_ / 32)   // mask words per row

// ---- GEMM tile config (mma.sync, LDGSTS-intensity optimized) ----
#define BM   256
#define BN   128
#define BK   64
#define GPAD 72
#define ASTG (BM * GPAD * 2)
#define BSTG (BN * GPAD * 2)
#define NCH  (K3 / BK)                 // 48
#define GEMM_SMEM (3 * (ASTG + BSTG))  // 165888 B

// ---------------- scratch (static device allocations) -----------------------
__device__ __nv_bfloat16 g_qh[B_ * H_ * S_ * DK_];
__device__ __nv_bfloat16 g_ql[B_ * H_ * S_ * DK_];
__device__ __nv_bfloat16 g_kh[B_ * H_ * S_ * DK_];
__device__ __nv_bfloat16 g_kl[B_ * H_ * S_ * DK_];
__device__ __nv_bfloat16 g_vh[B_ * H_ * S_ * DK_];
__device__ __nv_bfloat16 g_vl[B_ * H_ * S_ * DK_];
__device__ float g_ctx[B_ * S_ * D_];
__device__ float g_psum[B_ * 32];
__device__ float g_psq[B_ * 32];
__device__ uint32_t g_mbits[B_ * S_ * MW];

__device__ __nv_bfloat16 g_xb[M_ * K3];      // x packed   [Ah|Al|Ah]
__device__ __nv_bfloat16 g_cb[M_ * K3];      // ctx packed [Ah|Al|Ah]
__device__ __nv_bfloat16 g_wt[4 * D_ * K3];  // W^T packed [Bh|Bh|Bl]

// ---------------------------------------------------------------------------
// helpers
// ---------------------------------------------------------------------------
__device__ __forceinline__ uint32_t smem_u32(const void* p) {
    return (uint32_t)__cvta_generic_to_shared(p);
}
__device__ __forceinline__ void cp16(uint32_t dst, const void* src) {
    asm volatile("cp.async.cg.shared.global [%0], [%1], 16;\n" :: "r"(dst), "l"(src));
}
__device__ __forceinline__ void ldm_x4(uint32_t addr, uint32_t& r0, uint32_t& r1,
                                       uint32_t& r2, uint32_t& r3) {
    asm volatile("ldmatrix.sync.aligned.m8n8.x4.shared.b16 {%0,%1,%2,%3}, [%4];"
                 : "=r"(r0), "=r"(r1), "=r"(r2), "=r"(r3) : "r"(addr));
}
__device__ __forceinline__ void ldm_x4t(uint32_t addr, uint32_t& r0, uint32_t& r1,
                                        uint32_t& r2, uint32_t& r3) {
    asm volatile("ldmatrix.sync.aligned.m8n8.x4.trans.shared.b16 {%0,%1,%2,%3}, [%4];"
                 : "=r"(r0), "=r"(r1), "=r"(r2), "=r"(r3) : "r"(addr));
}
__device__ __forceinline__ void mma_bf16(float* c, const uint32_t* a,
                                         uint32_t b0, uint32_t b1) {
    asm volatile("mma.sync.aligned.m16n8k16.row.col.f32.bf16.bf16.f32 "
                 "{%0,%1,%2,%3},{%4,%5,%6,%7},{%8,%9},{%0,%1,%2,%3};"
                 : "+f"(c[0]), "+f"(c[1]), "+f"(c[2]), "+f"(c[3])
                 : "r"(a[0]), "r"(a[1]), "r"(a[2]), "r"(a[3]), "r"(b0), "r"(b1));
}
__device__ __forceinline__ uint32_t pack2(__nv_bfloat16 a, __nv_bfloat16 b) {
    __nv_bfloat162 t(a, b);
    return *(uint32_t*)&t;
}
__device__ __forceinline__ void split_bf16(float v, __nv_bfloat16& hi, __nv_bfloat16& lo) {
    hi = __float2bfloat16(v);
    lo = __float2bfloat16(v - __bfloat162float(hi));
}
__device__ __forceinline__ void packhl(float x, float y, uint32_t& hi, uint32_t& lo) {
    __nv_bfloat16 hx, lx, hy, ly;
    split_bf16(x, hx, lx); split_bf16(y, hy, ly);
    hi = pack2(hx, hy); lo = pack2(lx, ly);
}

// ---------------------------------------------------------------------------
// pack A-side fp32 [M,1024] -> bf16 [M,3072] = [hi | lo | hi]
// ---------------------------------------------------------------------------
__global__ __launch_bounds__(256) void conv_a_kernel(
    const float* __restrict__ src, __nv_bfloat16* __restrict__ dst)
{
    int idx = blockIdx.x * 256 + threadIdx.x;
    int m  = idx >> 8;
    int c4 = (idx & 255) * 4;
    float4 v = *(const float4*)(src + m * D_ + c4);
    __nv_bfloat16 h0, h1, h2, h3, l0, l1, l2, l3;
    split_bf16(v.x, h0, l0); split_bf16(v.y, h1, l1);
    split_bf16(v.z, h2, l2); split_bf16(v.w, h3, l3);
    uint2 hh = make_uint2(pack2(h0, h1), pack2(h2, h3));
    uint2 ll = make_uint2(pack2(l0, l1), pack2(l2, l3));
    __nv_bfloat16* row = dst + (size_t)m * K3 + c4;
    *(uint2*)(row)        = hh;
    *(uint2*)(row + 1024) = ll;
    *(uint2*)(row + 2048) = hh;
}

// ---------------------------------------------------------------------------
// pack + transpose B-side weights into g_wt[z][n][3072] = [hi | hi | lo]
// ---------------------------------------------------------------------------
__global__ __launch_bounds__(256) void conv_w_kernel(
    const float* __restrict__ wq, const float* __restrict__ wk,
    const float* __restrict__ wv, const float* __restrict__ wo)
{
    __shared__ float t[32][33];
    const int z  = blockIdx.z;
    const float* W = (z == 0) ? wq : (z == 1) ? wk : (z == 2) ? wv : wo;
    const int n0 = blockIdx.x * 32;
    const int k0 = blockIdx.y * 32;
    const int tx = threadIdx.x, ty = threadIdx.y;

    #pragma unroll
    for (int i = 0; i < 4; i++) {
        int k = k0 + ty + i * 8;
        int n = n0 + tx;
        float v = (z < 3) ? W[(n >> 6) * (D_ * DK_) + k * DK_ + (n & 63)]
                          : W[k * D_ + n];
        t[ty + i * 8][tx] = v;
    }
    __syncthreads();
    __nv_bfloat16* base = g_wt + (size_t)z * D_ * K3;
    #pragma unroll
    for (int i = 0; i < 4; i++) {
        int n = n0 + ty + i * 8;
        float v = t[tx][ty + i * 8];
        __nv_bfloat16 hi, lo;
        split_bf16(v, hi, lo);
        __nv_bfloat16* row = base + (size_t)n * K3 + k0 + tx;
        row[0]    = hi;
        row[1024] = hi;
        row[2048] = lo;
    }
}

// ---------------------------------------------------------------------------
// pack mask -> bits
// ---------------------------------------------------------------------------
__global__ __launch_bounds__(256) void mask_pack_kernel(const int* __restrict__ mask)
{
    int w = blockIdx.x * 8 + (threadIdx.x >> 5);
    int lane = threadIdx.x & 31;
    int v = mask[(size_t)w * 32 + lane];
    uint32_t bits = __ballot_sync(0xffffffffu, v != 0);
    if (lane == 0) g_mbits[w] = bits;
}

// ---------------------------------------------------------------------------
// GEMM core: 256x128 CTA tile, BK=64, 3-stage cp.async, 8 warps of 64x64.
// acc[4][8][4] per thread (warp covers 64 M x 64 N).
// ---------------------------------------------------------------------------
__device__ __forceinline__ void load_stage(
    const __nv_bfloat16* __restrict__ A, const __nv_bfloat16* __restrict__ Bt,
    int m0, int n0, uint32_t sA, uint32_t sB, int slot, int k, int tid)
{
    const uint32_t a = sA + slot * ASTG;
    const uint32_t b = sB + slot * BSTG;
    #pragma unroll
    for (int i = 0; i < 8; i++) {                 // A: 256 rows x 4 segs... 2048
        int seg = tid + i * 256;
        int row = seg >> 3, c = (seg & 7) * 8;
        cp16(a + (uint32_t)(row * GPAD + c) * 2, A + (size_t)(m0 + row) * K3 + k + c);
    }
    #pragma unroll
    for (int i = 0; i < 4; i++) {                 // B: 128 rows -> 1024 segs
        int seg = tid + i * 256;
        int row = seg >> 3, c = (seg & 7) * 8;
        cp16(b + (uint32_t)(row * GPAD + c) * 2, Bt + (size_t)(n0 + row) * K3 + k + c);
    }
    asm volatile("cp.async.commit_group;\n" ::: "memory");
}

__device__ __forceinline__ void gemm_core(
    const __nv_bfloat16* __restrict__ A,
    const __nv_bfloat16* __restrict__ Bt,
    int m0, int n0, float (&acc)[4][8][4])
{
    extern __shared__ __align__(16) char dsm[];
    const uint32_t sA = smem_u32(dsm);
    const uint32_t sB = sA + 3 * ASTG;

    const int tid  = threadIdx.x;
    const int lane = tid & 31;
    const int warp = tid >> 5;
    const int wm   = warp >> 1;   // 0..3  (M)
    const int wn   = warp & 1;    // 0..1  (N)

    const uint32_t aOff = ((wm * 64 + (lane & 15)) * GPAD + (lane >> 4) * 8) * 2;
    const uint32_t bOff = ((wn * 64 + (lane & 7) + ((lane >> 4) & 1) * 8) * GPAD
                           + ((lane >> 3) & 1) * 8) * 2;

    load_stage(A, Bt, m0, n0, sA, sB, 0, 0, tid);
    load_stage(A, Bt, m0, n0, sA, sB, 1, BK, tid);

    int slot = 0;
    for (int s = 0; s < NCH; s++) {
        if (s < NCH - 1)
            asm volatile("cp.async.wait_group 1;\n" ::: "memory");
        else
            asm volatile("cp.async.wait_group 0;\n" ::: "memory");
        __syncthreads();

        if (s + 2 < NCH) {
            int ns = slot + 2; if (ns >= 3) ns -= 3;
            load_stage(A, Bt, m0, n0, sA, sB, ns, (s + 2) * BK, tid);
        }

        const uint32_t aB = sA + slot * ASTG + aOff;
        const uint32_t bB = sB + slot * BSTG + bOff;
        #pragma unroll
        for (int kk = 0; kk < 4; kk++) {
            uint32_t af[4][4];
            #pragma unroll
            for (int mi = 0; mi < 4; mi++)
                ldm_x4(aB + mi * (16 * GPAD * 2) + kk * 32,
                       af[mi][0], af[mi][1], af[mi][2], af[mi][3]);
            #pragma unroll
            for (int nq = 0; nq < 4; nq++) {
                uint32_t b0, b1, b2, b3;
                ldm_x4(bB + nq * (16 * GPAD * 2) + kk * 32, b0, b1, b2, b3);
                #pragma unroll
                for (int mi = 0; mi < 4; mi++) {
                    mma_bf16(acc[mi][2 * nq],     af[mi], b0, b1);
                    mma_bf16(acc[mi][2 * nq + 1], af[mi], b2, b3);
                }
            }
        }
        slot = (slot + 1 == 3) ? 0 : slot + 1;
    }
}

// ---------------------------------------------------------------------------
// QKV GEMM (fused over z via N=3072 weight rows): writes split hi/lo bf16.
// grid: x = N-tile (24), y = M-tile (32)
// ---------------------------------------------------------------------------
__global__ __launch_bounds__(256, 1) void qkv_mma_kernel()
{
    const int n0 = blockIdx.x * BN;
    const int m0 = blockIdx.y * BM;

    float acc[4][8][4] = {};
    gemm_core(g_xb, g_wt, m0, n0, acc);

    const int lane = threadIdx.x & 31;
    const int warp = threadIdx.x >> 5;
    const int wm = warp >> 1, wn = warp & 1;
    const int mr = m0 + wm * 64 + (lane >> 2);
    const int nc = n0 + wn * 64 + (lane & 3) * 2;

    #pragma unroll
    for (int mi = 0; mi < 4; mi++) {
        #pragma unroll
        for (int nj = 0; nj < 8; nj++) {
            int n = nc + nj * 8;
            int z = n >> 10, h = (n >> 6) & 15, j = n & 63;
            const float scale = (z == 0) ? 0.125f : 1.0f;
            __nv_bfloat16* outH = (z == 0) ? g_qh : (z == 1) ? g_kh : g_vh;
            __nv_bfloat16* outL = (z == 0) ? g_ql : (z == 1) ? g_kl : g_vl;
            #pragma unroll
            for (int half = 0; half < 2; half++) {
                int m = mr + mi * 16 + half * 8;
                int b = m >> 10, ss = m & 1023;
                uint32_t hi, lo;
                packhl(acc[mi][nj][2 * half]     * scale,
                       acc[mi][nj][2 * half + 1] * scale, hi, lo);
                size_t idx = ((size_t)(b * H_ + h) * S_ + ss) * DK_ + j;
                *(uint32_t*)(outH + idx) = hi;
                *(uint32_t*)(outL + idx) = lo;
            }
        }
    }
}

// ---------------------------------------------------------------------------
// Out-proj GEMM: out = ctx @ wo + x ; deterministic LN partials (32/batch).
// grid: x = N-tile (8), y = M-tile (32)
// ---------------------------------------------------------------------------
__global__ __launch_bounds__(256, 1) void proj_mma_kernel(
    const float* __restrict__ x, float* __restrict__ out)
{
    __shared__ float red[2][8];
    const int n0 = blockIdx.x * BN;
    const int m0 = blockIdx.y * BM;

    float acc[4][8][4] = {};
    gemm_core(g_cb, g_wt + (size_t)3 * D_ * K3, m0, n0, acc);

    const int tid  = threadIdx.x;
    const int lane = tid & 31;
    const int warp = tid >> 5;
    const int wm = warp >> 1, wn = warp & 1;
    const int mr = m0 + wm * 64 + (lane >> 2);
    const int nc = n0 + wn * 64 + (lane & 3) * 2;

    float lsum = 0.f, lsq = 0.f;
    #pragma unroll
    for (int mi = 0; mi < 4; mi++) {
        #pragma unroll
        for (int nj = 0; nj < 8; nj++) {
            int n = nc + nj * 8;
            #pragma unroll
            for (int half = 0; half < 2; half++) {
                int m = mr + mi * 16 + half * 8;
                float v0 = acc[mi][nj][2 * half]     + x[(size_t)m * D_ + n];
                float v1 = acc[mi][nj][2 * half + 1] + x[(size_t)m * D_ + n + 1];
                lsum += v0 + v1;
                lsq  += v0 * v0 + v1 * v1;
                *(float2*)(out + (size_t)m * D_ + n) = make_float2(v0, v1);
            }
        }
    }

    #pragma unroll
    for (int w = 16; w > 0; w >>= 1) {
        lsum += __shfl_xor_sync(0xffffffffu, lsum, w);
        lsq  += __shfl_xor_sync(0xffffffffu, lsq, w);
    }
    if (lane == 0) { red[0][warp] = lsum; red[1][warp] = lsq; }
    __syncthreads();
    if (tid == 0) {
        float s = 0.f, q = 0.f;
        #pragma unroll
        for (int i = 0; i < 8; i++) { s += red[0][i]; q += red[1][i]; }
        int bb = m0 >> 10;
        int part = (blockIdx.y & 3) * 8 + blockIdx.x;   // 32 parts per batch
        g_psum[bb * 32 + part] = s;
        g_psq[bb * 32 + part]  = q;
    }
}

// ---------------------------------------------------------------------------
// Tensor-core flash attention (unchanged from R6, known-good).
// ---------------------------------------------------------------------------
__global__ __launch_bounds__(256, 2) void attn_tc_kernel()
{
    extern __shared__ __align__(16) __nv_bfloat16 sm[];
    __nv_bfloat16* sQ  = sm;
    __nv_bfloat16* sKV = sm + 2 * QT * PAD;

    const int bh = blockIdx.y, b = bh >> 4, h = bh & 15;
    const int s0 = blockIdx.x * QT;
    const int tid = threadIdx.x, lane = tid & 31, warp = tid >> 5;

    const __nv_bfloat16* gQh = g_qh + ((size_t)bh * S_ + s0) * DK_;
    const __nv_bfloat16* gQl = g_ql + ((size_t)bh * S_ + s0) * DK_;
    const __nv_bfloat16* gKh = g_kh + (size_t)bh * S_ * DK_;
    const __nv_bfloat16* gKl = g_kl + (size_t)bh * S_ * DK_;
    const __nv_bfloat16* gVh = g_vh + (size_t)bh * S_ * DK_;
    const __nv_bfloat16* gVl = g_vl + (size_t)bh * S_ * DK_;

    #pragma unroll
    for (int i = 0; i < 4; i++) {
        int c = tid + i * 256;
        int r = c >> 3, cl = (c & 7) * 8;
        cp16(smem_u32(sQ + r * PAD + cl),            gQh + r * DK_ + cl);
        cp16(smem_u32(sQ + QT * PAD + r * PAD + cl), gQl + r * DK_ + cl);
    }
    const uint32_t smKV = smem_u32(sKV);
    const uint32_t MATB = KT * PAD * 2;
    const uint32_t BUFB2 = 4 * MATB;
    #pragma unroll
    for (int i = 0; i < 2; i++) {
        int c = tid + i * 256;
        int r = c >> 3, cl = (c & 7) * 8;
        uint32_t d = smKV + (uint32_t)(r * PAD + cl) * 2;
        cp16(d,            gKh + r * DK_ + cl);
        cp16(d + MATB,     gKl + r * DK_ + cl);
        cp16(d + 2 * MATB, gVh + r * DK_ + cl);
        cp16(d + 3 * MATB, gVl + r * DK_ + cl);
    }
    asm volatile("cp.async.commit_group;\n" ::: "memory");

    const uint32_t smQ  = smem_u32(sQ);
    const uint32_t aOff = ((warp * 16 + (lane & 15)) * PAD + (lane >> 4) * 8) * 2;
    const uint32_t kOff = (((lane & 7) + ((lane >> 4) & 1) * 8) * PAD
                           + ((lane >> 3) & 1) * 8) * 2;
    const uint32_t vOff = (((lane & 7) + ((lane >> 3) & 1) * 8) * PAD
                           + ((lane >> 4) & 1) * 8) * 2;

    float oacc[8][4] = {};
    float mst[2] = {-1e30f, -1e30f}, lst[2] = {0.f, 0.f};

    const int r  = lane >> 2;
    const int q2 = (lane & 3) * 2;
    const uint32_t* mrow = g_mbits + ((size_t)b * S_ + s0 + warp * 16 + r) * MW;

    for (int t = 0; t < S_ / KT; t++) {
        const int buf = t & 1;
        if (t + 1 < S_ / KT) {
            const int t0n = (t + 1) * KT;
            #pragma unroll
            for (int i = 0; i < 2; i++) {
                int c = tid + i * 256;
                int rr = c >> 3, cl = (c & 7) * 8;
                uint32_t d = smKV + (buf ^ 1) * BUFB2 + (uint32_t)(rr * PAD + cl) * 2;
                cp16(d,            gKh + (t0n + rr) * DK_ + cl);
                cp16(d + MATB,     gKl + (t0n + rr) * DK_ + cl);
                cp16(d + 2 * MATB, gVh + (t0n + rr) * DK_ + cl);
                cp16(d + 3 * MATB, gVl + (t0n + rr) * DK_ + cl);
            }
            asm volatile("cp.async.commit_group;\n" ::: "memory");
            asm volatile("cp.async.wait_group 1;\n" ::: "memory");
        } else {
            asm volatile("cp.async.wait_group 0;\n" ::: "memory");
        }
        __syncthreads();

        float sacc[8][4] = {};
        const uint32_t kB = smKV + buf * BUFB2 + kOff;
        #pragma unroll
        for (int kk = 0; kk < 4; kk++) {
            uint32_t ah[4], al[4];
            ldm_x4(smQ + aOff + kk * 32,                ah[0], ah[1], ah[2], ah[3]);
            ldm_x4(smQ + QT * PAD * 2 + aOff + kk * 32, al[0], al[1], al[2], al[3]);
            #pragma unroll
            for (int nt = 0; nt < 4; nt++) {
                uint32_t b0, b1, b2, b3;
                ldm_x4(kB + nt * (16 * PAD * 2) + kk * 32, b0, b1, b2, b3);
                mma_bf16(sacc[2 * nt],     ah, b0, b1);
                mma_bf16(sacc[2 * nt + 1], ah, b2, b3);
                mma_bf16(sacc[2 * nt],     al, b0, b1);
                mma_bf16(sacc[2 * nt + 1], al, b2, b3);
                uint32_t c0, c1, c2, c3;
                ldm_x4(kB + MATB + nt * (16 * PAD * 2) + kk * 32, c0, c1, c2, c3);
                mma_bf16(sacc[2 * nt],     ah, c0, c1);
                mma_bf16(sacc[2 * nt + 1], ah, c2, c3);
            }
        }

        uint2 w0 = *(const uint2*)(mrow + (t * KT >> 5));
        uint2 w8 = *(const uint2*)(mrow + 8 * MW + (t * KT >> 5));
        #pragma unroll
        for (int nt = 0; nt < 8; nt++) {
            int c = nt * 8 + q2;
            uint32_t m0 = (c < 32) ? (w0.x >> c) : (w0.y >> (c - 32));
            uint32_t m8 = (c < 32) ? (w8.x >> c) : (w8.y >> (c - 32));
            sacc[nt][0] = (m0 & 1) ? sacc[nt][0] : -1e9f;
            sacc[nt][1] = (m0 & 2) ? sacc[nt][1] : -1e9f;
            sacc[nt][2] = (m8 & 1) ? sacc[nt][2] : -1e9f;
            sacc[nt][3] = (m8 & 2) ? sacc[nt][3] : -1e9f;
        }

        float alpha[2];
        #pragma unroll
        for (int hf = 0; hf < 2; hf++) {
            float mx = -1e30f;
            #pragma unroll
            for (int nt = 0; nt < 8; nt++)
                mx = fmaxf(mx, fmaxf(sacc[nt][2 * hf], sacc[nt][2 * hf + 1]));
            mx = fmaxf(mx, __shfl_xor_sync(0xffffffffu, mx, 1));
            mx = fmaxf(mx, __shfl_xor_sync(0xffffffffu, mx, 2));
            float mn = fmaxf(mst[hf], mx);
            alpha[hf] = __expf(mst[hf] - mn);
            mst[hf] = mn;
            float rs = 0.f;
            #pragma unroll
            for (int nt = 0; nt < 8; nt++) {
                float p0 = __expf(sacc[nt][2 * hf]     - mn);
                float p1 = __expf(sacc[nt][2 * hf + 1] - mn);
                sacc[nt][2 * hf] = p0; sacc[nt][2 * hf + 1] = p1;
                rs += p0 + p1;
            }
            rs += __shfl_xor_sync(0xffffffffu, rs, 1);
            rs += __shfl_xor_sync(0xffffffffu, rs, 2);
            lst[hf] = lst[hf] * alpha[hf] + rs;
        }
        #pragma unroll
        for (int nt = 0; nt < 8; nt++) {
            oacc[nt][0] *= alpha[0]; oacc[nt][1] *= alpha[0];
            oacc[nt][2] *= alpha[1]; oacc[nt][3] *= alpha[1];
        }

        const uint32_t vB = smKV + buf * BUFB2 + 2 * MATB + vOff;
        #pragma unroll
        for (int kk = 0; kk < 4; kk++) {
            uint32_t pa[4], pl[4];
            packhl(sacc[2 * kk][0],     sacc[2 * kk][1],     pa[0], pl[0]);
            packhl(sacc[2 * kk][2],     sacc[2 * kk][3],     pa[1], pl[1]);
            packhl(sacc[2 * kk + 1][0], sacc[2 * kk + 1][1], pa[2], pl[2]);
            packhl(sacc[2 * kk + 1][2], sacc[2 * kk + 1][3], pa[3], pl[3]);
            #pragma unroll
            for (int nt = 0; nt < 4; nt++) {
                uint32_t v0, v1, v2, v3;
                ldm_x4t(vB + kk * (16 * PAD * 2) + nt * 32, v0, v1, v2, v3);
                mma_bf16(oacc[2 * nt],     pa, v0, v1);
                mma_bf16(oacc[2 * nt + 1], pa, v2, v3);
                mma_bf16(oacc[2 * nt],     pl, v0, v1);
                mma_bf16(oacc[2 * nt + 1], pl, v2, v3);
                uint32_t u0, u1, u2, u3;
                ldm_x4t(vB + MATB + kk * (16 * PAD * 2) + nt * 32, u0, u1, u2, u3);
                mma_bf16(oacc[2 * nt],     pa, u0, u1);
                mma_bf16(oacc[2 * nt + 1], pa, u2, u3);
            }
        }
        __syncthreads();
    }

    const float inv0 = 1.f / lst[0], inv1 = 1.f / lst[1];
    float* b0p = g_ctx + ((size_t)b * S_ + s0 + warp * 16 + r) * D_ + h * DK_;
    float* b8p = b0p + 8 * D_;
    #pragma unroll
    for (int nt = 0; nt < 8; nt++) {
        *(float2*)(b0p + nt * 8 + q2) =
            make_float2(oacc[nt][0] * inv0, oacc[nt][1] * inv0);
        *(float2*)(b8p + nt * 8 + q2) =
            make_float2(oacc[nt][2] * inv1, oacc[nt][3] * inv1);
    }
}

// ---------------------------------------------------------------------------
// LayerNorm over (S, D) per batch from the 32 deterministic partials.
// ---------------------------------------------------------------------------
__global__ __launch_bounds__(256) void ln_kernel(float* __restrict__ out)
{
    const int blk = blockIdx.x;
    const int b = blk >> 8;
    float s = 0.f, q = 0.f;
    #pragma unroll
    for (int i = 0; i < 32; i++) { s += g_psum[b * 32 + i]; q += g_psq[b * 32 + i]; }
    const float invN = 1.f / (float)(S_ * D_);
    const float mean = s * invN;
    const float var  = q * invN - mean * mean;
    const float rstd = rsqrtf(var + 1e-5f);

    float* p = out + (size_t)blk * 4096;
    #pragma unroll
    for (int i = 0; i < 4; i++) {
        float4 v = *(float4*)(p + (threadIdx.x + i * 256) * 4);
        v.x = (v.x - mean) * rstd; v.y = (v.y - mean) * rstd;
        v.z = (v.z - mean) * rstd; v.w = (v.w - mean) * rstd;
        *(float4*)(p + (threadIdx.x + i * 256) * 4) = v;
    }
}

// ---------------------------------------------------------------------------
extern "C" void kernel_launch(void* const* d_in, const int* in_sizes, int n_in,
                              void* d_out, int out_size)
{
    (void)in_sizes; (void)n_in; (void)out_size;
    const int*   mask = (const int*)  d_in[0];
    const float* x    = (const float*)d_in[1];
    const float* wq   = (const float*)d_in[2];
    const float* wk   = (const float*)d_in[3];
    const float* wv   = (const float*)d_in[4];
    const float* wo   = (const float*)d_in[5];
    float* out = (float*)d_out;

    __nv_bfloat16* xb;  cudaGetSymbolAddress((void**)&xb,  g_xb);
    __nv_bfloat16* cb;  cudaGetSymbolAddress((void**)&cb,  g_cb);
    float* ctx;         cudaGetSymbolAddress((void**)&ctx, g_ctx);

    const int ATTN_SMEM = (2 * QT * PAD + 8 * KT * PAD) * 2;
    cudaFuncSetAttribute(attn_tc_kernel,
                         cudaFuncAttributeMaxDynamicSharedMemorySize, ATTN_SMEM);
    cudaFuncSetAttribute(qkv_mma_kernel,
                         cudaFuncAttributeMaxDynamicSharedMemorySize, GEMM_SMEM);
    cudaFuncSetAttribute(proj_mma_kernel,
                         cudaFuncAttributeMaxDynamicSharedMemorySize, GEMM_SMEM);

    mask_pack_kernel<<<(B_ * S_ * MW) / 8, 256>>>(mask);
    conv_a_kernel<<<M_ * (D_ / 1024), 256>>>(x, xb);
    conv_w_kernel<<<dim3(32, 32, 4), dim3(32, 8)>>>(wq, wk, wv, wo);
    qkv_mma_kernel<<<dim3(3 * D_ / BN, M_ / BM), 256, GEMM_SMEM>>>();
    attn_tc_kernel<<<dim3(S_ / QT, B_ * H_), 256, ATTN_SMEM>>>();
    conv_a_kernel<<<M_ * (D_ / 1024), 256>>>(ctx, cb);
    proj_mma_kernel<<<dim3(D_ / BN, M_ / BM), 256, GEMM_SMEM>>>(x, out);
    ln_kernel<<<(B_ * S_ * D_) / 4096, 256>>>(out);
}

// round 9
// speedup vs baseline: 3.7646x; 1.4136x over previous
#include <cuda_runtime.h>
#include <cuda_fp16.h>
#include <math.h>
#include <stdint.h>

#define B_  8
#define S_  1024
#define D_  1024
#define H_  16
#define DK_ 64
#define M_  (B_ * S_)   // 8192
#define K2  2048        // split-K: A=[hi|lo], B=[hi|hi]

#define QT  128         // attention: query rows per block
#define KT  64          // attention: keys per tile
#define PAD 72          // attn smem row stride
#define MW  (S_ / 32)   // mask words per row

// ---- GEMM tile config ----
#define BM   256
#define BN   128
#define BK   64
#define GPAD 72
#define ASTG (BM * GPAD * 2)
#define BSTG (BN * GPAD * 2)
#define NCH  (K2 / BK)                 // 32
#define GEMM_SMEM (3 * (ASTG + BSTG))  // 165888 B

// ---------------- scratch (static device allocations) -----------------------
__device__ __half g_qh[B_ * H_ * S_ * DK_];
__device__ __half g_ql[B_ * H_ * S_ * DK_];
__device__ __half g_kh[B_ * H_ * S_ * DK_];
__device__ __half g_vh[B_ * H_ * S_ * DK_];
__device__ float g_ctx[B_ * S_ * D_];
__device__ float g_psum[B_ * 32];
__device__ float g_psq[B_ * 32];
__device__ uint32_t g_mbits[B_ * S_ * MW];

__device__ __half g_xb[M_ * K2];      // x packed   [Ah|Al]
__device__ __half g_cb[M_ * K2];      // ctx packed [Ah|Al]
__device__ __half g_wt[4 * D_ * K2];  // W^T packed [Bh|Bh]

// ---------------------------------------------------------------------------
// helpers
// ---------------------------------------------------------------------------
__device__ __forceinline__ uint32_t smem_u32(const void* p) {
    return (uint32_t)__cvta_generic_to_shared(p);
}
__device__ __forceinline__ void cp16(uint32_t dst, const void* src) {
    asm volatile("cp.async.cg.shared.global [%0], [%1], 16;\n" :: "r"(dst), "l"(src));
}
__device__ __forceinline__ void ldm_x4(uint32_t addr, uint32_t& r0, uint32_t& r1,
                                       uint32_t& r2, uint32_t& r3) {
    asm volatile("ldmatrix.sync.aligned.m8n8.x4.shared.b16 {%0,%1,%2,%3}, [%4];"
                 : "=r"(r0), "=r"(r1), "=r"(r2), "=r"(r3) : "r"(addr));
}
__device__ __forceinline__ void ldm_x4t(uint32_t addr, uint32_t& r0, uint32_t& r1,
                                        uint32_t& r2, uint32_t& r3) {
    asm volatile("ldmatrix.sync.aligned.m8n8.x4.trans.shared.b16 {%0,%1,%2,%3}, [%4];"
                 : "=r"(r0), "=r"(r1), "=r"(r2), "=r"(r3) : "r"(addr));
}
__device__ __forceinline__ void mma_f16(float* c, const uint32_t* a,
                                        uint32_t b0, uint32_t b1) {
    asm volatile("mma.sync.aligned.m16n8k16.row.col.f32.f16.f16.f32 "
                 "{%0,%1,%2,%3},{%4,%5,%6,%7},{%8,%9},{%0,%1,%2,%3};"
                 : "+f"(c[0]), "+f"(c[1]), "+f"(c[2]), "+f"(c[3])
                 : "r"(a[0]), "r"(a[1]), "r"(a[2]), "r"(a[3]), "r"(b0), "r"(b1));
}
__device__ __forceinline__ uint32_t pack2(__half a, __half b) {
    __half2 t(a, b);
    return *(uint32_t*)&t;
}
__device__ __forceinline__ void split_f16(float v, __half& hi, __half& lo) {
    hi = __float2half(v);
    lo = __float2half(v - __half2float(hi));
}
__device__ __forceinline__ void packhl(float x, float y, uint32_t& hi, uint32_t& lo) {
    __half hx, lx, hy, ly;
    split_f16(x, hx, lx); split_f16(y, hy, ly);
    hi = pack2(hx, hy); lo = pack2(lx, ly);
}

// ---------------------------------------------------------------------------
// pack A-side fp32 [M,1024] -> fp16 [M,2048] = [hi | lo]
// ---------------------------------------------------------------------------
__global__ __launch_bounds__(256) void conv_a_kernel(
    const float* __restrict__ src, __half* __restrict__ dst)
{
    int idx = blockIdx.x * 256 + threadIdx.x;
    int m  = idx >> 8;
    int c4 = (idx & 255) * 4;
    float4 v = *(const float4*)(src + m * D_ + c4);
    __half h0, h1, h2, h3, l0, l1, l2, l3;
    split_f16(v.x, h0, l0); split_f16(v.y, h1, l1);
    split_f16(v.z, h2, l2); split_f16(v.w, h3, l3);
    uint2 hh = make_uint2(pack2(h0, h1), pack2(h2, h3));
    uint2 ll = make_uint2(pack2(l0, l1), pack2(l2, l3));
    __half* row = dst + (size_t)m * K2 + c4;
    *(uint2*)(row)        = hh;
    *(uint2*)(row + 1024) = ll;
}

// ---------------------------------------------------------------------------
// pack + transpose B-side weights into g_wt[z][n][2048] = [hi | hi]
// ---------------------------------------------------------------------------
__global__ __launch_bounds__(256) void conv_w_kernel(
    const float* __restrict__ wq, const float* __restrict__ wk,
    const float* __restrict__ wv, const float* __restrict__ wo)
{
    __shared__ float t[32][33];
    const int z  = blockIdx.z;
    const float* W = (z == 0) ? wq : (z == 1) ? wk : (z == 2) ? wv : wo;
    const int n0 = blockIdx.x * 32;
    const int k0 = blockIdx.y * 32;
    const int tx = threadIdx.x, ty = threadIdx.y;

    #pragma unroll
    for (int i = 0; i < 4; i++) {
        int k = k0 + ty + i * 8;
        int n = n0 + tx;
        float v = (z < 3) ? W[(n >> 6) * (D_ * DK_) + k * DK_ + (n & 63)]
                          : W[k * D_ + n];
        t[ty + i * 8][tx] = v;
    }
    __syncthreads();
    __half* base = g_wt + (size_t)z * D_ * K2;
    #pragma unroll
    for (int i = 0; i < 4; i++) {
        int n = n0 + ty + i * 8;
        __half hi = __float2half(t[tx][ty + i * 8]);
        __half* row = base + (size_t)n * K2 + k0 + tx;
        row[0]    = hi;
        row[1024] = hi;
    }
}

// ---------------------------------------------------------------------------
// pack mask -> bits
// ---------------------------------------------------------------------------
__global__ __launch_bounds__(256) void mask_pack_kernel(const int* __restrict__ mask)
{
    int w = blockIdx.x * 8 + (threadIdx.x >> 5);
    int lane = threadIdx.x & 31;
    int v = mask[(size_t)w * 32 + lane];
    uint32_t bits = __ballot_sync(0xffffffffu, v != 0);
    if (lane == 0) g_mbits[w] = bits;
}

// ---------------------------------------------------------------------------
// GEMM core: 256x128 CTA tile, BK=64, 3-stage cp.async, 8 warps of 64x64.
// ---------------------------------------------------------------------------
__device__ __forceinline__ void load_stage(
    const __half* __restrict__ A, const __half* __restrict__ Bt,
    int m0, int n0, uint32_t sA, uint32_t sB, int slot, int k, int tid)
{
    const uint32_t a = sA + slot * ASTG;
    const uint32_t b = sB + slot * BSTG;
    #pragma unroll
    for (int i = 0; i < 8; i++) {
        int seg = tid + i * 256;
        int row = seg >> 3, c = (seg & 7) * 8;
        cp16(a + (uint32_t)(row * GPAD + c) * 2, A + (size_t)(m0 + row) * K2 + k + c);
    }
    #pragma unroll
    for (int i = 0; i < 4; i++) {
        int seg = tid + i * 256;
        int row = seg >> 3, c = (seg & 7) * 8;
        cp16(b + (uint32_t)(row * GPAD + c) * 2, Bt + (size_t)(n0 + row) * K2 + k + c);
    }
    asm volatile("cp.async.commit_group;\n" ::: "memory");
}

__device__ __forceinline__ void gemm_core(
    const __half* __restrict__ A,
    const __half* __restrict__ Bt,
    int m0, int n0, float (&acc)[4][8][4])
{
    extern __shared__ __align__(16) char dsm[];
    const uint32_t sA = smem_u32(dsm);
    const uint32_t sB = sA + 3 * ASTG;

    const int tid  = threadIdx.x;
    const int lane = tid & 31;
    const int warp = tid >> 5;
    const int wm   = warp >> 1;
    const int wn   = warp & 1;

    const uint32_t aOff = ((wm * 64 + (lane & 15)) * GPAD + (lane >> 4) * 8) * 2;
    const uint32_t bOff = ((wn * 64 + (lane & 7) + ((lane >> 4) & 1) * 8) * GPAD
                           + ((lane >> 3) & 1) * 8) * 2;

    load_stage(A, Bt, m0, n0, sA, sB, 0, 0, tid);
    load_stage(A, Bt, m0, n0, sA, sB, 1, BK, tid);

    int slot = 0;
    for (int s = 0; s < NCH; s++) {
        if (s < NCH - 1)
            asm volatile("cp.async.wait_group 1;\n" ::: "memory");
        else
            asm volatile("cp.async.wait_group 0;\n" ::: "memory");
        __syncthreads();

        if (s + 2 < NCH) {
            int ns = slot + 2; if (ns >= 3) ns -= 3;
            load_stage(A, Bt, m0, n0, sA, sB, ns, (s + 2) * BK, tid);
        }

        const uint32_t aB = sA + slot * ASTG + aOff;
        const uint32_t bB = sB + slot * BSTG + bOff;
        #pragma unroll
        for (int kk = 0; kk < 4; kk++) {
            uint32_t af[4][4];
            #pragma unroll
            for (int mi = 0; mi < 4; mi++)
                ldm_x4(aB + mi * (16 * GPAD * 2) + kk * 32,
                       af[mi][0], af[mi][1], af[mi][2], af[mi][3]);
            #pragma unroll
            for (int nq = 0; nq < 4; nq++) {
                uint32_t b0, b1, b2, b3;
                ldm_x4(bB + nq * (16 * GPAD * 2) + kk * 32, b0, b1, b2, b3);
                #pragma unroll
                for (int mi = 0; mi < 4; mi++) {
                    mma_f16(acc[mi][2 * nq],     af[mi], b0, b1);
                    mma_f16(acc[mi][2 * nq + 1], af[mi], b2, b3);
                }
            }
        }
        slot = (slot + 1 == 3) ? 0 : slot + 1;
    }
}

// ---------------------------------------------------------------------------
// QKV GEMM (fused over z): writes split hi (+lo for Q) fp16 [B,H,S,DK].
// ---------------------------------------------------------------------------
__global__ __launch_bounds__(256, 1) void qkv_mma_kernel()
{
    const int n0 = blockIdx.x * BN;
    const int m0 = blockIdx.y * BM;

    float acc[4][8][4] = {};
    gemm_core(g_xb, g_wt, m0, n0, acc);

    const int lane = threadIdx.x & 31;
    const int warp = threadIdx.x >> 5;
    const int wm = warp >> 1, wn = warp & 1;
    const int mr = m0 + wm * 64 + (lane >> 2);
    const int nc = n0 + wn * 64 + (lane & 3) * 2;

    #pragma unroll
    for (int mi = 0; mi < 4; mi++) {
        #pragma unroll
        for (int nj = 0; nj < 8; nj++) {
            int n = nc + nj * 8;
            int z = n >> 10, h = (n >> 6) & 15, j = n & 63;
            const float scale = (z == 0) ? 0.125f : 1.0f;
            __half* outH = (z == 0) ? g_qh : (z == 1) ? g_kh : g_vh;
            #pragma unroll
            for (int half = 0; half < 2; half++) {
                int m = mr + mi * 16 + half * 8;
                int b = m >> 10, ss = m & 1023;
                uint32_t hi, lo;
                packhl(acc[mi][nj][2 * half]     * scale,
                       acc[mi][nj][2 * half + 1] * scale, hi, lo);
                size_t idx = ((size_t)(b * H_ + h) * S_ + ss) * DK_ + j;
                *(uint32_t*)(outH + idx) = hi;
                if (z == 0) *(uint32_t*)(g_ql + idx) = lo;
            }
        }
    }
}

// ---------------------------------------------------------------------------
// Out-proj GEMM: out = ctx @ wo + x ; deterministic LN partials (32/batch).
// ---------------------------------------------------------------------------
__global__ __launch_bounds__(256, 1) void proj_mma_kernel(
    const float* __restrict__ x, float* __restrict__ out)
{
    __shared__ float red[2][8];
    const int n0 = blockIdx.x * BN;
    const int m0 = blockIdx.y * BM;

    float acc[4][8][4] = {};
    gemm_core(g_cb, g_wt + (size_t)3 * D_ * K2, m0, n0, acc);

    const int tid  = threadIdx.x;
    const int lane = tid & 31;
    const int warp = tid >> 5;
    const int wm = warp >> 1, wn = warp & 1;
    const int mr = m0 + wm * 64 + (lane >> 2);
    const int nc = n0 + wn * 64 + (lane & 3) * 2;

    float lsum = 0.f, lsq = 0.f;
    #pragma unroll
    for (int mi = 0; mi < 4; mi++) {
        #pragma unroll
        for (int nj = 0; nj < 8; nj++) {
            int n = nc + nj * 8;
            #pragma unroll
            for (int half = 0; half < 2; half++) {
                int m = mr + mi * 16 + half * 8;
                float v0 = acc[mi][nj][2 * half]     + x[(size_t)m * D_ + n];
                float v1 = acc[mi][nj][2 * half + 1] + x[(size_t)m * D_ + n + 1];
                lsum += v0 + v1;
                lsq  += v0 * v0 + v1 * v1;
                *(float2*)(out + (size_t)m * D_ + n) = make_float2(v0, v1);
            }
        }
    }

    #pragma unroll
    for (int w = 16; w > 0; w >>= 1) {
        lsum += __shfl_xor_sync(0xffffffffu, lsum, w);
        lsq  += __shfl_xor_sync(0xffffffffu, lsq, w);
    }
    if (lane == 0) { red[0][warp] = lsum; red[1][warp] = lsq; }
    __syncthreads();
    if (tid == 0) {
        float s = 0.f, q = 0.f;
        #pragma unroll
        for (int i = 0; i < 8; i++) { s += red[0][i]; q += red[1][i]; }
        int bb = m0 >> 10;
        int part = (blockIdx.y & 3) * 8 + blockIdx.x;
        g_psum[bb * 32 + part] = s;
        g_psq[bb * 32 + part]  = q;
    }
}

// ---------------------------------------------------------------------------
// Tensor-core flash attention, fp16 2-pass:
// S = Qh*Kh^T + Ql*Kh^T ; O += Ph*Vh + Pl*Vh.  KV smem: {Kh, Vh} x2 buffers.
// ---------------------------------------------------------------------------
__global__ __launch_bounds__(256, 2) void attn_tc_kernel()
{
    extern __shared__ __align__(16) __half sm[];
    __half* sQ  = sm;                        // Qh [128*72] then Ql [128*72]
    __half* sKV = sm + 2 * QT * PAD;         // 2 bufs x (Kh, Vh)[64*72]

    const int bh = blockIdx.y, b = bh >> 4, h = bh & 15;
    const int s0 = blockIdx.x * QT;
    const int tid = threadIdx.x, lane = tid & 31, warp = tid >> 5;

    const __half* gQh = g_qh + ((size_t)bh * S_ + s0) * DK_;
    const __half* gQl = g_ql + ((size_t)bh * S_ + s0) * DK_;
    const __half* gKh = g_kh + (size_t)bh * S_ * DK_;
    const __half* gVh = g_vh + (size_t)bh * S_ * DK_;

    #pragma unroll
    for (int i = 0; i < 4; i++) {
        int c = tid + i * 256;
        int r = c >> 3, cl = (c & 7) * 8;
        cp16(smem_u32(sQ + r * PAD + cl),            gQh + r * DK_ + cl);
        cp16(smem_u32(sQ + QT * PAD + r * PAD + cl), gQl + r * DK_ + cl);
    }
    const uint32_t smKV = smem_u32(sKV);
    const uint32_t MATB = KT * PAD * 2;
    const uint32_t BUFB2 = 2 * MATB;
    #pragma unroll
    for (int i = 0; i < 2; i++) {
        int c = tid + i * 256;
        int r = c >> 3, cl = (c & 7) * 8;
        uint32_t d = smKV + (uint32_t)(r * PAD + cl) * 2;
        cp16(d,        gKh + r * DK_ + cl);
        cp16(d + MATB, gVh + r * DK_ + cl);
    }
    asm volatile("cp.async.commit_group;\n" ::: "memory");

    const uint32_t smQ  = smem_u32(sQ);
    const uint32_t aOff = ((warp * 16 + (lane & 15)) * PAD + (lane >> 4) * 8) * 2;
    const uint32_t kOff = (((lane & 7) + ((lane >> 4) & 1) * 8) * PAD
                           + ((lane >> 3) & 1) * 8) * 2;
    const uint32_t vOff = (((lane & 7) + ((lane >> 3) & 1) * 8) * PAD
                           + ((lane >> 4) & 1) * 8) * 2;

    float oacc[8][4] = {};
    float mst[2] = {-1e30f, -1e30f}, lst[2] = {0.f, 0.f};

    const int r  = lane >> 2;
    const int q2 = (lane & 3) * 2;
    const uint32_t* mrow = g_mbits + ((size_t)b * S_ + s0 + warp * 16 + r) * MW;

    for (int t = 0; t < S_ / KT; t++) {
        const int buf = t & 1;
        if (t + 1 < S_ / KT) {
            const int t0n = (t + 1) * KT;
            #pragma unroll
            for (int i = 0; i < 2; i++) {
                int c = tid + i * 256;
                int rr = c >> 3, cl = (c & 7) * 8;
                uint32_t d = smKV + (buf ^ 1) * BUFB2 + (uint32_t)(rr * PAD + cl) * 2;
                cp16(d,        gKh + (t0n + rr) * DK_ + cl);
                cp16(d + MATB, gVh + (t0n + rr) * DK_ + cl);
            }
            asm volatile("cp.async.commit_group;\n" ::: "memory");
            asm volatile("cp.async.wait_group 1;\n" ::: "memory");
        } else {
            asm volatile("cp.async.wait_group 0;\n" ::: "memory");
        }
        __syncthreads();

        // ---- S = Qh*Kh^T + Ql*Kh^T ----
        float sacc[8][4] = {};
        const uint32_t kB = smKV + buf * BUFB2 + kOff;
        #pragma unroll
        for (int kk = 0; kk < 4; kk++) {
            uint32_t ah[4], al[4];
            ldm_x4(smQ + aOff + kk * 32,                ah[0], ah[1], ah[2], ah[3]);
            ldm_x4(smQ + QT * PAD * 2 + aOff + kk * 32, al[0], al[1], al[2], al[3]);
            #pragma unroll
            for (int nt = 0; nt < 4; nt++) {
                uint32_t b0, b1, b2, b3;
                ldm_x4(kB + nt * (16 * PAD * 2) + kk * 32, b0, b1, b2, b3);
                mma_f16(sacc[2 * nt],     ah, b0, b1);
                mma_f16(sacc[2 * nt + 1], ah, b2, b3);
                mma_f16(sacc[2 * nt],     al, b0, b1);
                mma_f16(sacc[2 * nt + 1], al, b2, b3);
            }
        }

        // ---- mask (bit-packed) ----
        uint2 w0 = *(const uint2*)(mrow + (t * KT >> 5));
        uint2 w8 = *(const uint2*)(mrow + 8 * MW + (t * KT >> 5));
        #pragma unroll
        for (int nt = 0; nt < 8; nt++) {
            int c = nt * 8 + q2;
            uint32_t m0 = (c < 32) ? (w0.x >> c) : (w0.y >> (c - 32));
            uint32_t m8 = (c < 32) ? (w8.x >> c) : (w8.y >> (c - 32));
            sacc[nt][0] = (m0 & 1) ? sacc[nt][0] : -1e9f;
            sacc[nt][1] = (m0 & 2) ? sacc[nt][1] : -1e9f;
            sacc[nt][2] = (m8 & 1) ? sacc[nt][2] : -1e9f;
            sacc[nt][3] = (m8 & 2) ? sacc[nt][3] : -1e9f;
        }

        // ---- online softmax ----
        float alpha[2];
        #pragma unroll
        for (int hf = 0; hf < 2; hf++) {
            float mx = -1e30f;
            #pragma unroll
            for (int nt = 0; nt < 8; nt++)
                mx = fmaxf(mx, fmaxf(sacc[nt][2 * hf], sacc[nt][2 * hf + 1]));
            mx = fmaxf(mx, __shfl_xor_sync(0xffffffffu, mx, 1));
            mx = fmaxf(mx, __shfl_xor_sync(0xffffffffu, mx, 2));
            float mn = fmaxf(mst[hf], mx);
            alpha[hf] = __expf(mst[hf] - mn);
            mst[hf] = mn;
            float rs = 0.f;
            #pragma unroll
            for (int nt = 0; nt < 8; nt++) {
                float p0 = __expf(sacc[nt][2 * hf]     - mn);
                float p1 = __expf(sacc[nt][2 * hf + 1] - mn);
                sacc[nt][2 * hf] = p0; sacc[nt][2 * hf + 1] = p1;
                rs += p0 + p1;
            }
            rs += __shfl_xor_sync(0xffffffffu, rs, 1);
            rs += __shfl_xor_sync(0xffffffffu, rs, 2);
            lst[hf] = lst[hf] * alpha[hf] + rs;
        }
        #pragma unroll
        for (int nt = 0; nt < 8; nt++) {
            oacc[nt][0] *= alpha[0]; oacc[nt][1] *= alpha[0];
            oacc[nt][2] *= alpha[1]; oacc[nt][3] *= alpha[1];
        }

        // ---- O += Ph*Vh + Pl*Vh ----
        const uint32_t vB = smKV + buf * BUFB2 + MATB + vOff;
        #pragma unroll
        for (int kk = 0; kk < 4; kk++) {
            uint32_t pa[4], pl[4];
            packhl(sacc[2 * kk][0],     sacc[2 * kk][1],     pa[0], pl[0]);
            packhl(sacc[2 * kk][2],     sacc[2 * kk][3],     pa[1], pl[1]);
            packhl(sacc[2 * kk + 1][0], sacc[2 * kk + 1][1], pa[2], pl[2]);
            packhl(sacc[2 * kk + 1][2], sacc[2 * kk + 1][3], pa[3], pl[3]);
            #pragma unroll
            for (int nt = 0; nt < 4; nt++) {
                uint32_t v0, v1, v2, v3;
                ldm_x4t(vB + kk * (16 * PAD * 2) + nt * 32, v0, v1, v2, v3);
                mma_f16(oacc[2 * nt],     pa, v0, v1);
                mma_f16(oacc[2 * nt + 1], pa, v2, v3);
                mma_f16(oacc[2 * nt],     pl, v0, v1);
                mma_f16(oacc[2 * nt + 1], pl, v2, v3);
            }
        }
        __syncthreads();
    }

    const float inv0 = 1.f / lst[0], inv1 = 1.f / lst[1];
    float* b0p = g_ctx + ((size_t)b * S_ + s0 + warp * 16 + r) * D_ + h * DK_;
    float* b8p = b0p + 8 * D_;
    #pragma unroll
    for (int nt = 0; nt < 8; nt++) {
        *(float2*)(b0p + nt * 8 + q2) =
            make_float2(oacc[nt][0] * inv0, oacc[nt][1] * inv0);
        *(float2*)(b8p + nt * 8 + q2) =
            make_float2(oacc[nt][2] * inv1, oacc[nt][3] * inv1);
    }
}

// ---------------------------------------------------------------------------
// LayerNorm over (S, D) per batch from the 32 deterministic partials.
// ---------------------------------------------------------------------------
__global__ __launch_bounds__(256) void ln_kernel(float* __restrict__ out)
{
    const int blk = blockIdx.x;
    const int b = blk >> 8;
    float s = 0.f, q = 0.f;
    #pragma unroll
    for (int i = 0; i < 32; i++) { s += g_psum[b * 32 + i]; q += g_psq[b * 32 + i]; }
    const float invN = 1.f / (float)(S_ * D_);
    const float mean = s * invN;
    const float var  = q * invN - mean * mean;
    const float rstd = rsqrtf(var + 1e-5f);

    float* p = out + (size_t)blk * 4096;
    #pragma unroll
    for (int i = 0; i < 4; i++) {
        float4 v = *(float4*)(p + (threadIdx.x + i * 256) * 4);
        v.x = (v.x - mean) * rstd; v.y = (v.y - mean) * rstd;
        v.z = (v.z - mean) * rstd; v.w = (v.w - mean) * rstd;
        *(float4*)(p + (threadIdx.x + i * 256) * 4) = v;
    }
}

// ---------------------------------------------------------------------------
extern "C" void kernel_launch(void* const* d_in, const int* in_sizes, int n_in,
                              void* d_out, int out_size)
{
    (void)in_sizes; (void)n_in; (void)out_size;
    const int*   mask = (const int*)  d_in[0];
    const float* x    = (const float*)d_in[1];
    const float* wq   = (const float*)d_in[2];
    const float* wk   = (const float*)d_in[3];
    const float* wv   = (const float*)d_in[4];
    const float* wo   = (const float*)d_in[5];
    float* out = (float*)d_out;

    __half* xb;  cudaGetSymbolAddress((void**)&xb,  g_xb);
    __half* cb;  cudaGetSymbolAddress((void**)&cb,  g_cb);
    float* ctx;  cudaGetSymbolAddress((void**)&ctx, g_ctx);

    const int ATTN_SMEM = (2 * QT * PAD + 4 * KT * PAD) * 2;   // 73728 B
    cudaFuncSetAttribute(attn_tc_kernel,
                         cudaFuncAttributeMaxDynamicSharedMemorySize, ATTN_SMEM);
    cudaFuncSetAttribute(qkv_mma_kernel,
                         cudaFuncAttributeMaxDynamicSharedMemorySize, GEMM_SMEM);
    cudaFuncSetAttribute(proj_mma_kernel,
                         cudaFuncAttributeMaxDynamicSharedMemorySize, GEMM_SMEM);

    mask_pack_kernel<<<(B_ * S_ * MW) / 8, 256>>>(mask);
    conv_a_kernel<<<M_ * (D_ / 1024), 256>>>(x, xb);
    conv_w_kernel<<<dim3(32, 32, 4), dim3(32, 8)>>>(wq, wk, wv, wo);
    qkv_mma_kernel<<<dim3(3 * D_ / BN, M_ / BM), 256, GEMM_SMEM>>>();
    attn_tc_kernel<<<dim3(S_ / QT, B_ * H_), 256, ATTN_SMEM>>>();
    conv_a_kernel<<<M_ * (D_ / 1024), 256>>>(ctx, cb);
    proj_mma_kernel<<<dim3(D_ / BN, M_ / BM), 256, GEMM_SMEM>>>(x, out);
    ln_kernel<<<(B_ * S_ * D_) / 4096, 256>>>(out);
}

// round 10
// speedup vs baseline: 6.2083x; 1.6491x over previous
#include <cuda_runtime.h>
#include <cuda_fp16.h>
#include <math.h>
#include <stdint.h>

#define B_  8
#define S_  1024
#define D_  1024
#define H_  16
#define DK_ 64
#define M_  (B_ * S_)   // 8192
#define K1  1024        // single-pass fp16: K = D

#define QT  128         // attention: query rows per block
#define KT  64          // attention: keys per tile
#define PAD 72          // attn smem row stride
#define MW  (S_ / 32)   // mask words per row

// ---- GEMM tile config ----
#define BM   256
#define BN   128
#define BK   64
#define GPAD 72
#define ASTG (BM * GPAD * 2)
#define BSTG (BN * GPAD * 2)
#define NCH  (K1 / BK)                 // 16
#define GEMM_SMEM (3 * (ASTG + BSTG))  // 165888 B

// ---------------- scratch (static device allocations) -----------------------
__device__ __half g_qh[B_ * H_ * S_ * DK_];
__device__ __half g_kh[B_ * H_ * S_ * DK_];
__device__ __half g_vh[B_ * H_ * S_ * DK_];
__device__ float g_psum[B_ * 32];
__device__ float g_psq[B_ * 32];
__device__ uint32_t g_mbits[B_ * S_ * MW];

__device__ __half g_xb[M_ * K1];      // x   (fp16 hi)
__device__ __half g_cb[M_ * K1];      // ctx (fp16 hi), written by attention
__device__ __half g_wt[4 * D_ * K1];  // W^T (fp16 hi)

// ---------------------------------------------------------------------------
// helpers
// ---------------------------------------------------------------------------
__device__ __forceinline__ uint32_t smem_u32(const void* p) {
    return (uint32_t)__cvta_generic_to_shared(p);
}
__device__ __forceinline__ void cp16(uint32_t dst, const void* src) {
    asm volatile("cp.async.cg.shared.global [%0], [%1], 16;\n" :: "r"(dst), "l"(src));
}
__device__ __forceinline__ void ldm_x4(uint32_t addr, uint32_t& r0, uint32_t& r1,
                                       uint32_t& r2, uint32_t& r3) {
    asm volatile("ldmatrix.sync.aligned.m8n8.x4.shared.b16 {%0,%1,%2,%3}, [%4];"
                 : "=r"(r0), "=r"(r1), "=r"(r2), "=r"(r3) : "r"(addr));
}
__device__ __forceinline__ void ldm_x4t(uint32_t addr, uint32_t& r0, uint32_t& r1,
                                        uint32_t& r2, uint32_t& r3) {
    asm volatile("ldmatrix.sync.aligned.m8n8.x4.trans.shared.b16 {%0,%1,%2,%3}, [%4];"
                 : "=r"(r0), "=r"(r1), "=r"(r2), "=r"(r3) : "r"(addr));
}
__device__ __forceinline__ void mma_f16(float* c, const uint32_t* a,
                                        uint32_t b0, uint32_t b1) {
    asm volatile("mma.sync.aligned.m16n8k16.row.col.f32.f16.f16.f32 "
                 "{%0,%1,%2,%3},{%4,%5,%6,%7},{%8,%9},{%0,%1,%2,%3};"
                 : "+f"(c[0]), "+f"(c[1]), "+f"(c[2]), "+f"(c[3])
                 : "r"(a[0]), "r"(a[1]), "r"(a[2]), "r"(a[3]), "r"(b0), "r"(b1));
}
__device__ __forceinline__ uint32_t pack2(__half a, __half b) {
    __half2 t(a, b);
    return *(uint32_t*)&t;
}
__device__ __forceinline__ uint32_t packf(float x, float y) {
    return pack2(__float2half(x), __float2half(y));
}

// ---------------------------------------------------------------------------
// convert x fp32 [M,1024] -> fp16 [M,1024]
// ---------------------------------------------------------------------------
__global__ __launch_bounds__(256) void conv_a_kernel(
    const float* __restrict__ src, __half* __restrict__ dst)
{
    int idx = blockIdx.x * 256 + threadIdx.x;
    float4 v = *(const float4*)(src + (size_t)idx * 4);
    uint2 hh = make_uint2(packf(v.x, v.y), packf(v.z, v.w));
    *(uint2*)(dst + (size_t)idx * 4) = hh;
}

// ---------------------------------------------------------------------------
// pack + transpose B-side weights into g_wt[z][n][1024] fp16
// ---------------------------------------------------------------------------
__global__ __launch_bounds__(256) void conv_w_kernel(
    const float* __restrict__ wq, const float* __restrict__ wk,
    const float* __restrict__ wv, const float* __restrict__ wo)
{
    __shared__ float t[32][33];
    const int z  = blockIdx.z;
    const float* W = (z == 0) ? wq : (z == 1) ? wk : (z == 2) ? wv : wo;
    const int n0 = blockIdx.x * 32;
    const int k0 = blockIdx.y * 32;
    const int tx = threadIdx.x, ty = threadIdx.y;

    #pragma unroll
    for (int i = 0; i < 4; i++) {
        int k = k0 + ty + i * 8;
        int n = n0 + tx;
        float v = (z < 3) ? W[(n >> 6) * (D_ * DK_) + k * DK_ + (n & 63)]
                          : W[k * D_ + n];
        t[ty + i * 8][tx] = v;
    }
    __syncthreads();
    __half* base = g_wt + (size_t)z * D_ * K1;
    #pragma unroll
    for (int i = 0; i < 4; i++) {
        int n = n0 + ty + i * 8;
        base[(size_t)n * K1 + k0 + tx] = __float2half(t[tx][ty + i * 8]);
    }
}

// ---------------------------------------------------------------------------
// pack mask -> bits
// ---------------------------------------------------------------------------
__global__ __launch_bounds__(256) void mask_pack_kernel(const int* __restrict__ mask)
{
    int w = blockIdx.x * 8 + (threadIdx.x >> 5);
    int lane = threadIdx.x & 31;
    int v = mask[(size_t)w * 32 + lane];
    uint32_t bits = __ballot_sync(0xffffffffu, v != 0);
    if (lane == 0) g_mbits[w] = bits;
}

// ---------------------------------------------------------------------------
// GEMM core: 256x128 CTA tile, BK=64, 3-stage cp.async, 8 warps of 64x64.
// ---------------------------------------------------------------------------
__device__ __forceinline__ void load_stage(
    const __half* __restrict__ A, const __half* __restrict__ Bt,
    int m0, int n0, uint32_t sA, uint32_t sB, int slot, int k, int tid)
{
    const uint32_t a = sA + slot * ASTG;
    const uint32_t b = sB + slot * BSTG;
    #pragma unroll
    for (int i = 0; i < 8; i++) {
        int seg = tid + i * 256;
        int row = seg >> 3, c = (seg & 7) * 8;
        cp16(a + (uint32_t)(row * GPAD + c) * 2, A + (size_t)(m0 + row) * K1 + k + c);
    }
    #pragma unroll
    for (int i = 0; i < 4; i++) {
        int seg = tid + i * 256;
        int row = seg >> 3, c = (seg & 7) * 8;
        cp16(b + (uint32_t)(row * GPAD + c) * 2, Bt + (size_t)(n0 + row) * K1 + k + c);
    }
    asm volatile("cp.async.commit_group;\n" ::: "memory");
}

__device__ __forceinline__ void gemm_core(
    const __half* __restrict__ A,
    const __half* __restrict__ Bt,
    int m0, int n0, float (&acc)[4][8][4])
{
    extern __shared__ __align__(16) char dsm[];
    const uint32_t sA = smem_u32(dsm);
    const uint32_t sB = sA + 3 * ASTG;

    const int tid  = threadIdx.x;
    const int lane = tid & 31;
    const int warp = tid >> 5;
    const int wm   = warp >> 1;
    const int wn   = warp & 1;

    const uint32_t aOff = ((wm * 64 + (lane & 15)) * GPAD + (lane >> 4) * 8) * 2;
    const uint32_t bOff = ((wn * 64 + (lane & 7) + ((lane >> 4) & 1) * 8) * GPAD
                           + ((lane >> 3) & 1) * 8) * 2;

    load_stage(A, Bt, m0, n0, sA, sB, 0, 0, tid);
    load_stage(A, Bt, m0, n0, sA, sB, 1, BK, tid);

    int slot = 0;
    for (int s = 0; s < NCH; s++) {
        if (s < NCH - 1)
            asm volatile("cp.async.wait_group 1;\n" ::: "memory");
        else
            asm volatile("cp.async.wait_group 0;\n" ::: "memory");
        __syncthreads();

        if (s + 2 < NCH) {
            int ns = slot + 2; if (ns >= 3) ns -= 3;
            load_stage(A, Bt, m0, n0, sA, sB, ns, (s + 2) * BK, tid);
        }

        const uint32_t aB = sA + slot * ASTG + aOff;
        const uint32_t bB = sB + slot * BSTG + bOff;
        #pragma unroll
        for (int kk = 0; kk < 4; kk++) {
            uint32_t af[4][4];
            #pragma unroll
            for (int mi = 0; mi < 4; mi++)
                ldm_x4(aB + mi * (16 * GPAD * 2) + kk * 32,
                       af[mi][0], af[mi][1], af[mi][2], af[mi][3]);
            #pragma unroll
            for (int nq = 0; nq < 4; nq++) {
                uint32_t b0, b1, b2, b3;
                ldm_x4(bB + nq * (16 * GPAD * 2) + kk * 32, b0, b1, b2, b3);
                #pragma unroll
                for (int mi = 0; mi < 4; mi++) {
                    mma_f16(acc[mi][2 * nq],     af[mi], b0, b1);
                    mma_f16(acc[mi][2 * nq + 1], af[mi], b2, b3);
                }
            }
        }
        slot = (slot + 1 == 3) ? 0 : slot + 1;
    }
}

// ---------------------------------------------------------------------------
// QKV GEMM (fused over z): writes fp16 Q/K/V [B,H,S,DK]; Q scaled by 0.125.
// ---------------------------------------------------------------------------
__global__ __launch_bounds__(256, 1) void qkv_mma_kernel()
{
    const int n0 = blockIdx.x * BN;
    const int m0 = blockIdx.y * BM;

    float acc[4][8][4] = {};
    gemm_core(g_xb, g_wt, m0, n0, acc);

    const int lane = threadIdx.x & 31;
    const int warp = threadIdx.x >> 5;
    const int wm = warp >> 1, wn = warp & 1;
    const int mr = m0 + wm * 64 + (lane >> 2);
    const int nc = n0 + wn * 64 + (lane & 3) * 2;

    #pragma unroll
    for (int mi = 0; mi < 4; mi++) {
        #pragma unroll
        for (int nj = 0; nj < 8; nj++) {
            int n = nc + nj * 8;
            int z = n >> 10, h = (n >> 6) & 15, j = n & 63;
            const float scale = (z == 0) ? 0.125f : 1.0f;
            __half* outH = (z == 0) ? g_qh : (z == 1) ? g_kh : g_vh;
            #pragma unroll
            for (int half = 0; half < 2; half++) {
                int m = mr + mi * 16 + half * 8;
                int b = m >> 10, ss = m & 1023;
                uint32_t hi = packf(acc[mi][nj][2 * half]     * scale,
                                    acc[mi][nj][2 * half + 1] * scale);
                size_t idx = ((size_t)(b * H_ + h) * S_ + ss) * DK_ + j;
                *(uint32_t*)(outH + idx) = hi;
            }
        }
    }
}

// ---------------------------------------------------------------------------
// Out-proj GEMM: out = ctx(fp16) @ wo + x ; deterministic LN partials.
// ---------------------------------------------------------------------------
__global__ __launch_bounds__(256, 1) void proj_mma_kernel(
    const float* __restrict__ x, float* __restrict__ out)
{
    __shared__ float red[2][8];
    const int n0 = blockIdx.x * BN;
    const int m0 = blockIdx.y * BM;

    float acc[4][8][4] = {};
    gemm_core(g_cb, g_wt + (size_t)3 * D_ * K1, m0, n0, acc);

    const int tid  = threadIdx.x;
    const int lane = tid & 31;
    const int warp = tid >> 5;
    const int wm = warp >> 1, wn = warp & 1;
    const int mr = m0 + wm * 64 + (lane >> 2);
    const int nc = n0 + wn * 64 + (lane & 3) * 2;

    float lsum = 0.f, lsq = 0.f;
    #pragma unroll
    for (int mi = 0; mi < 4; mi++) {
        #pragma unroll
        for (int nj = 0; nj < 8; nj++) {
            int n = nc + nj * 8;
            #pragma unroll
            for (int half = 0; half < 2; half++) {
                int m = mr + mi * 16 + half * 8;
                float v0 = acc[mi][nj][2 * half]     + x[(size_t)m * D_ + n];
                float v1 = acc[mi][nj][2 * half + 1] + x[(size_t)m * D_ + n + 1];
                lsum += v0 + v1;
                lsq  += v0 * v0 + v1 * v1;
                *(float2*)(out + (size_t)m * D_ + n) = make_float2(v0, v1);
            }
        }
    }

    #pragma unroll
    for (int w = 16; w > 0; w >>= 1) {
        lsum += __shfl_xor_sync(0xffffffffu, lsum, w);
        lsq  += __shfl_xor_sync(0xffffffffu, lsq, w);
    }
    if (lane == 0) { red[0][warp] = lsum; red[1][warp] = lsq; }
    __syncthreads();
    if (tid == 0) {
        float s = 0.f, q = 0.f;
        #pragma unroll
        for (int i = 0; i < 8; i++) { s += red[0][i]; q += red[1][i]; }
        int bb = m0 >> 10;
        int part = (blockIdx.y & 3) * 8 + blockIdx.x;
        g_psum[bb * 32 + part] = s;
        g_psq[bb * 32 + part]  = q;
    }
}

// ---------------------------------------------------------------------------
// Tensor-core flash attention, fp16 single-pass:
// S = Qh*Kh^T ; O += Ph*Vh. ctx written directly as fp16 into g_cb.
// ---------------------------------------------------------------------------
__global__ __launch_bounds__(256, 2) void attn_tc_kernel()
{
    extern __shared__ __align__(16) __half sm[];
    __half* sQ  = sm;                        // Qh [128*72]
    __half* sKV = sm + QT * PAD;             // 2 bufs x (Kh, Vh)[64*72]

    const int bh = blockIdx.y, b = bh >> 4, h = bh & 15;
    const int s0 = blockIdx.x * QT;
    const int tid = threadIdx.x, lane = tid & 31, warp = tid >> 5;

    const __half* gQh = g_qh + ((size_t)bh * S_ + s0) * DK_;
    const __half* gKh = g_kh + (size_t)bh * S_ * DK_;
    const __half* gVh = g_vh + (size_t)bh * S_ * DK_;

    #pragma unroll
    for (int i = 0; i < 4; i++) {
        int c = tid + i * 256;
        int r = c >> 3, cl = (c & 7) * 8;
        cp16(smem_u32(sQ + r * PAD + cl), gQh + r * DK_ + cl);
    }
    const uint32_t smKV = smem_u32(sKV);
    const uint32_t MATB = KT * PAD * 2;
    const uint32_t BUFB2 = 2 * MATB;
    #pragma unroll
    for (int i = 0; i < 2; i++) {
        int c = tid + i * 256;
        int r = c >> 3, cl = (c & 7) * 8;
        uint32_t d = smKV + (uint32_t)(r * PAD + cl) * 2;
        cp16(d,        gKh + r * DK_ + cl);
        cp16(d + MATB, gVh + r * DK_ + cl);
    }
    asm volatile("cp.async.commit_group;\n" ::: "memory");

    const uint32_t smQ  = smem_u32(sQ);
    const uint32_t aOff = ((warp * 16 + (lane & 15)) * PAD + (lane >> 4) * 8) * 2;
    const uint32_t kOff = (((lane & 7) + ((lane >> 4) & 1) * 8) * PAD
                           + ((lane >> 3) & 1) * 8) * 2;
    const uint32_t vOff = (((lane & 7) + ((lane >> 3) & 1) * 8) * PAD
                           + ((lane >> 4) & 1) * 8) * 2;

    float oacc[8][4] = {};
    float mst[2] = {-1e30f, -1e30f}, lst[2] = {0.f, 0.f};

    const int r  = lane >> 2;
    const int q2 = (lane & 3) * 2;
    const uint32_t* mrow = g_mbits + ((size_t)b * S_ + s0 + warp * 16 + r) * MW;

    for (int t = 0; t < S_ / KT; t++) {
        const int buf = t & 1;
        if (t + 1 < S_ / KT) {
            const int t0n = (t + 1) * KT;
            #pragma unroll
            for (int i = 0; i < 2; i++) {
                int c = tid + i * 256;
                int rr = c >> 3, cl = (c & 7) * 8;
                uint32_t d = smKV + (buf ^ 1) * BUFB2 + (uint32_t)(rr * PAD + cl) * 2;
                cp16(d,        gKh + (t0n + rr) * DK_ + cl);
                cp16(d + MATB, gVh + (t0n + rr) * DK_ + cl);
            }
            asm volatile("cp.async.commit_group;\n" ::: "memory");
            asm volatile("cp.async.wait_group 1;\n" ::: "memory");
        } else {
            asm volatile("cp.async.wait_group 0;\n" ::: "memory");
        }
        __syncthreads();

        // ---- S = Qh*Kh^T ----
        float sacc[8][4] = {};
        const uint32_t kB = smKV + buf * BUFB2 + kOff;
        #pragma unroll
        for (int kk = 0; kk < 4; kk++) {
            uint32_t ah[4];
            ldm_x4(smQ + aOff + kk * 32, ah[0], ah[1], ah[2], ah[3]);
            #pragma unroll
            for (int nt = 0; nt < 4; nt++) {
                uint32_t b0, b1, b2, b3;
                ldm_x4(kB + nt * (16 * PAD * 2) + kk * 32, b0, b1, b2, b3);
                mma_f16(sacc[2 * nt],     ah, b0, b1);
                mma_f16(sacc[2 * nt + 1], ah, b2, b3);
            }
        }

        // ---- mask (bit-packed) ----
        uint2 w0 = *(const uint2*)(mrow + (t * KT >> 5));
        uint2 w8 = *(const uint2*)(mrow + 8 * MW + (t * KT >> 5));
        #pragma unroll
        for (int nt = 0; nt < 8; nt++) {
            int c = nt * 8 + q2;
            uint32_t m0 = (c < 32) ? (w0.x >> c) : (w0.y >> (c - 32));
            uint32_t m8 = (c < 32) ? (w8.x >> c) : (w8.y >> (c - 32));
            sacc[nt][0] = (m0 & 1) ? sacc[nt][0] : -1e9f;
            sacc[nt][1] = (m0 & 2) ? sacc[nt][1] : -1e9f;
            sacc[nt][2] = (m8 & 1) ? sacc[nt][2] : -1e9f;
            sacc[nt][3] = (m8 & 2) ? sacc[nt][3] : -1e9f;
        }

        // ---- online softmax ----
        float alpha[2];
        #pragma unroll
        for (int hf = 0; hf < 2; hf++) {
            float mx = -1e30f;
            #pragma unroll
            for (int nt = 0; nt < 8; nt++)
                mx = fmaxf(mx, fmaxf(sacc[nt][2 * hf], sacc[nt][2 * hf + 1]));
            mx = fmaxf(mx, __shfl_xor_sync(0xffffffffu, mx, 1));
            mx = fmaxf(mx, __shfl_xor_sync(0xffffffffu, mx, 2));
            float mn = fmaxf(mst[hf], mx);
            alpha[hf] = __expf(mst[hf] - mn);
            mst[hf] = mn;
            float rs = 0.f;
            #pragma unroll
            for (int nt = 0; nt < 8; nt++) {
                float p0 = __expf(sacc[nt][2 * hf]     - mn);
                float p1 = __expf(sacc[nt][2 * hf + 1] - mn);
                sacc[nt][2 * hf] = p0; sacc[nt][2 * hf + 1] = p1;
                rs += p0 + p1;
            }
            rs += __shfl_xor_sync(0xffffffffu, rs, 1);
            rs += __shfl_xor_sync(0xffffffffu, rs, 2);
            lst[hf] = lst[hf] * alpha[hf] + rs;
        }
        #pragma unroll
        for (int nt = 0; nt < 8; nt++) {
            oacc[nt][0] *= alpha[0]; oacc[nt][1] *= alpha[0];
            oacc[nt][2] *= alpha[1]; oacc[nt][3] *= alpha[1];
        }

        // ---- O += Ph*Vh ----
        const uint32_t vB = smKV + buf * BUFB2 + MATB + vOff;
        #pragma unroll
        for (int kk = 0; kk < 4; kk++) {
            uint32_t pa[4];
            pa[0] = packf(sacc[2 * kk][0],     sacc[2 * kk][1]);
            pa[1] = packf(sacc[2 * kk][2],     sacc[2 * kk][3]);
            pa[2] = packf(sacc[2 * kk + 1][0], sacc[2 * kk + 1][1]);
            pa[3] = packf(sacc[2 * kk + 1][2], sacc[2 * kk + 1][3]);
            #pragma unroll
            for (int nt = 0; nt < 4; nt++) {
                uint32_t v0, v1, v2, v3;
                ldm_x4t(vB + kk * (16 * PAD * 2) + nt * 32, v0, v1, v2, v3);
                mma_f16(oacc[2 * nt],     pa, v0, v1);
                mma_f16(oacc[2 * nt + 1], pa, v2, v3);
            }
        }
        __syncthreads();
    }

    // ---- normalize + write ctx as fp16 into g_cb[b*S+s][h*64+dk] ----
    const float inv0 = 1.f / lst[0], inv1 = 1.f / lst[1];
    __half* b0p = g_cb + ((size_t)b * S_ + s0 + warp * 16 + r) * D_ + h * DK_;
    __half* b8p = b0p + 8 * D_;
    #pragma unroll
    for (int nt = 0; nt < 8; nt++) {
        *(uint32_t*)(b0p + nt * 8 + q2) =
            packf(oacc[nt][0] * inv0, oacc[nt][1] * inv0);
        *(uint32_t*)(b8p + nt * 8 + q2) =
            packf(oacc[nt][2] * inv1, oacc[nt][3] * inv1);
    }
}

// ---------------------------------------------------------------------------
// LayerNorm over (S, D) per batch from the 32 deterministic partials.
// ---------------------------------------------------------------------------
__global__ __launch_bounds__(256) void ln_kernel(float* __restrict__ out)
{
    const int blk = blockIdx.x;
    const int b = blk >> 8;
    float s = 0.f, q = 0.f;
    #pragma unroll
    for (int i = 0; i < 32; i++) { s += g_psum[b * 32 + i]; q += g_psq[b * 32 + i]; }
    const float invN = 1.f / (float)(S_ * D_);
    const float mean = s * invN;
    const float var  = q * invN - mean * mean;
    const float rstd = rsqrtf(var + 1e-5f);

    float* p = out + (size_t)blk * 4096;
    #pragma unroll
    for (int i = 0; i < 4; i++) {
        float4 v = *(float4*)(p + (threadIdx.x + i * 256) * 4);
        v.x = (v.x - mean) * rstd; v.y = (v.y - mean) * rstd;
        v.z = (v.z - mean) * rstd; v.w = (v.w - mean) * rstd;
        *(float4*)(p + (threadIdx.x + i * 256) * 4) = v;
    }
}

// ---------------------------------------------------------------------------
extern "C" void kernel_launch(void* const* d_in, const int* in_sizes, int n_in,
                              void* d_out, int out_size)
{
    (void)in_sizes; (void)n_in; (void)out_size;
    const int*   mask = (const int*)  d_in[0];
    const float* x    = (const float*)d_in[1];
    const float* wq   = (const float*)d_in[2];
    const float* wk   = (const float*)d_in[3];
    const float* wv   = (const float*)d_in[4];
    const float* wo   = (const float*)d_in[5];
    float* out = (float*)d_out;

    __half* xb;  cudaGetSymbolAddress((void**)&xb, g_xb);

    const int ATTN_SMEM = (QT * PAD + 4 * KT * PAD) * 2;   // 55296 B
    cudaFuncSetAttribute(attn_tc_kernel,
                         cudaFuncAttributeMaxDynamicSharedMemorySize, ATTN_SMEM);
    cudaFuncSetAttribute(qkv_mma_kernel,
                         cudaFuncAttributeMaxDynamicSharedMemorySize, GEMM_SMEM);
    cudaFuncSetAttribute(proj_mma_kernel,
                         cudaFuncAttributeMaxDynamicSharedMemorySize, GEMM_SMEM);

    mask_pack_kernel<<<(B_ * S_ * MW) / 8, 256>>>(mask);
    conv_a_kernel<<<(M_ * D_) / 1024, 256>>>(x, xb);
    conv_w_kernel<<<dim3(32, 32, 4), dim3(32, 8)>>>(wq, wk, wv, wo);
    qkv_mma_kernel<<<dim3(3 * D_ / BN, M_ / BM), 256, GEMM_SMEM>>>();
    attn_tc_kernel<<<dim3(S_ / QT, B_ * H_), 256, ATTN_SMEM>>>();
    proj_mma_kernel<<<dim3(D_ / BN, M_ / BM), 256, GEMM_SMEM>>>(x, out);
    ln_kernel<<<(B_ * S_ * D_) / 4096, 256>>>(out);
}